// round 2
// baseline (speedup 1.0000x reference)
#include <cuda_runtime.h>
#include <cuda_fp16.h>
#include <cstdint>
#include <cstddef>

#define B_ 4
#define T_ 512
#define H_ 128
#define D_ 300
#define V_ 50257
#define E_ 64

// ---------------- static device scratch ----------------
__device__ float  g_xw  [B_*T_*4*H_];       // gates pre-activation (x path + biases)
__device__ float  g_h   [B_*T_*H_];         // LSTM hidden states
__device__ float  g_weh [B_*T_*H_];         // We @ h
__device__ float  g_wdh [B_*T_*H_];         // Wd @ h
__device__ float  g_fsrc[B_*T_*H_];         // selected feature source vector
__device__ int    g_sel [B_*T_];            // eid > 0 flag
__device__ __half g_z16 [B_*T_*H_];         // z = h + ent_feat (fp16)
__device__ __half g_wx16[(size_t)V_*H_];    // Wx in fp16

// ---------------- K0: Wx -> fp16 ----------------
__global__ void k_cvt(const float* __restrict__ src, __half* __restrict__ dst, int n) {
    int i = blockIdx.x * blockDim.x + threadIdx.x;
    if (i < n) dst[i] = __float2half(src[i]);
}

// ---------------- K1: xw = embed[tok] @ Wih^T + bih + bhh ----------------
// grid (T/16, B), 512 threads; thread n computes gate column n for 16 timesteps
__global__ void k_xw(const int* __restrict__ tokens, const float* __restrict__ embed,
                     const float* __restrict__ Wih, const float* __restrict__ bih,
                     const float* __restrict__ bhh) {
    __shared__ __align__(16) float xs[16][D_];
    int b = blockIdx.y, t0 = blockIdx.x * 16, n = threadIdx.x;
    for (int i = n; i < 16 * D_; i += 512) {
        int r = i / D_, d = i - r * D_;
        xs[r][d] = embed[(size_t)tokens[b * T_ + t0 + r] * D_ + d];
    }
    __syncthreads();
    float acc[16];
#pragma unroll
    for (int r = 0; r < 16; r++) acc[r] = 0.f;
    const float4* wr = reinterpret_cast<const float4*>(Wih + (size_t)n * D_);
#pragma unroll 5
    for (int d4 = 0; d4 < D_ / 4; d4++) {
        float4 w = __ldg(wr + d4);
#pragma unroll
        for (int r = 0; r < 16; r++) {
            float4 x = *reinterpret_cast<const float4*>(&xs[r][d4 * 4]);
            acc[r] += w.x * x.x + w.y * x.y + w.z * x.z + w.w * x.w;
        }
    }
    float bb = bih[n] + bhh[n];
    for (int r = 0; r < 16; r++)
        g_xw[((size_t)(b * T_ + t0 + r) << 9) + n] = acc[r] + bb;
}

// ---------------- K2: sequential LSTM, one CTA per batch ----------------
__global__ void k_lstm(const float* __restrict__ Whh, const float* __restrict__ Wr,
                       const float* __restrict__ br, float* __restrict__ out_pr) {
    __shared__ __align__(16) float hs[H_];
    __shared__ float gsm[4 * H_];
    __shared__ float red[4];
    __shared__ float wrs[H_];
    int b = blockIdx.x, n = threadIdx.x;
    if (n < H_) { hs[n] = 0.f; wrs[n] = Wr[n]; }
    float c = 0.f;
    __syncthreads();
    const float4* wrow = reinterpret_cast<const float4*>(Whh + (size_t)n * H_);
    for (int t = 0; t < T_; t++) {
        int bt = b * T_ + t;
        float acc = g_xw[((size_t)bt << 9) + n];
        const float4* h4 = reinterpret_cast<const float4*>(hs);
#pragma unroll 8
        for (int k = 0; k < H_ / 4; k++) {
            float4 w = __ldg(wrow + k);
            float4 h = h4[k];
            acc += w.x * h.x + w.y * h.y + w.z * h.z + w.w * h.w;
        }
        gsm[n] = acc;
        __syncthreads();
        if (n < H_) {
            float gi = gsm[n], gf = gsm[n + 128], gg = gsm[n + 256], go = gsm[n + 384];
            float si = 1.f / (1.f + __expf(-gi));
            float sf = 1.f / (1.f + __expf(-gf));
            float so = 1.f / (1.f + __expf(-go));
            c = sf * c + si * tanhf(gg);
            float h = so * tanhf(c);
            hs[n] = h;
            g_h[(size_t)bt * H_ + n] = h;
            float p = h * wrs[n];
#pragma unroll
            for (int o = 16; o; o >>= 1) p += __shfl_down_sync(0xffffffffu, p, o);
            if ((n & 31) == 0) red[n >> 5] = p;
        }
        __syncthreads();
        if (n == 0) {
            float s = red[0] + red[1] + red[2] + red[3] + br[0];
            out_pr[bt] = 1.f / (1.f + __expf(-s));
        }
    }
}

// ---------------- K3: veh = We@h, vdh = Wd@h, all (b,t) ----------------
// grid 128 CTAs x 16 rows, 256 threads: tid<128 -> We col, else Wd col
__global__ void k_vw(const float* __restrict__ We, const float* __restrict__ Wd) {
    __shared__ __align__(16) float hsm[16][H_];
    int row0 = blockIdx.x * 16;
    int tid = threadIdx.x;
    for (int i = tid; i < 16 * H_; i += 256)
        hsm[i >> 7][i & 127] = g_h[(size_t)row0 * H_ + i];
    __syncthreads();
    int k = tid & 127;
    const float* M = (tid < 128) ? We : Wd;
    float* O = (tid < 128) ? g_weh : g_wdh;
    const float4* mrow = reinterpret_cast<const float4*>(M + (size_t)k * H_);
    float acc[16];
#pragma unroll
    for (int r = 0; r < 16; r++) acc[r] = 0.f;
#pragma unroll 4
    for (int k4 = 0; k4 < H_ / 4; k4++) {
        float4 w = __ldg(mrow + k4);
#pragma unroll
        for (int r = 0; r < 16; r++) {
            float4 h = *reinterpret_cast<const float4*>(&hsm[r][k4 * 4]);
            acc[r] += w.x * h.x + w.y * h.y + w.z * h.z + w.w * h.w;
        }
    }
    for (int r = 0; r < 16; r++)
        O[(size_t)(row0 + r) * H_ + k] = acc[r];
}

// ---------------- K4: sequential entity recurrence, one CTA per batch ----------------
__global__ void k_ent(const int* __restrict__ eids, const int* __restrict__ sids,
                      const float* __restrict__ ents0, const float* __restrict__ lamp,
                      float* __restrict__ out_pe) {
    __shared__ float entsT[H_][E_ + 1];   // transposed + padded: conflict-free
    __shared__ float dists[E_];
    __shared__ float veh_s[H_], vdh_s[H_], h_s[H_], last_s[H_];
    __shared__ float red2[256];
    __shared__ float nred[4];    // delta partials
    __shared__ float nred2[4];   // norm partials
    int b = blockIdx.x, tid = threadIdx.x;
    float lam = *lamp;
    for (int i = tid; i < E_ * H_; i += 256) {
        int e = i >> 7, j = i & 127;
        entsT[j][e] = ents0[(size_t)(b * E_ + e) * H_ + j];
    }
    if (tid < E_) dists[tid] = 0.f;
    if (tid < H_) last_s[tid] = ents0[(size_t)b * E_ * H_ + tid];  // e0[0]
    __syncthreads();
    int q = tid >> 6, e = tid & 63;
    int lane = tid & 31, warp = tid >> 5;
    for (int t = 0; t < T_; t++) {
        int bt = b * T_ + t;
        if (tid < H_) {
            veh_s[tid] = g_weh[(size_t)bt * H_ + tid];
            vdh_s[tid] = g_wdh[(size_t)bt * H_ + tid];
            h_s[tid]   = g_h[(size_t)bt * H_ + tid];
        }
        int eid = eids[bt];
        float sid = (float)sids[bt];
        __syncthreads();  // S1: loads + prev-step entsT stable
        // pred_e partials: thread (q,e) sums j in [32q, 32q+32)
        float p = 0.f;
#pragma unroll
        for (int jj = 0; jj < 32; jj++) {
            int j = q * 32 + jj;
            p += entsT[j][e] * veh_s[j];
        }
        red2[tid] = p;
        // delta partials (pre-update ents[eid] . vdh)
        float dd = 0.f;
        if (tid < H_) dd = entsT[tid][eid] * vdh_s[tid];
#pragma unroll
        for (int o = 16; o; o >>= 1) dd += __shfl_down_sync(0xffffffffu, dd, o);
        if (tid < H_ && lane == 0) nred[warp] = dd;
        __syncthreads();  // S2
        if (tid < E_) {
            float pe = red2[tid] + red2[tid + 64] + red2[tid + 128] + red2[tid + 192]
                     + expf((dists[tid] - sid) * lam);
            out_pe[(size_t)bt * E_ + tid] = pe;
        }
        float delta = 1.f / (1.f + __expf(-(nred[0] + nred[1] + nred[2] + nred[3])));
        float u = 0.f;
        if (tid < H_) {
            u = delta * entsT[tid][eid] + (1.f - delta) * h_s[tid];
            float u2 = u * u;
#pragma unroll
            for (int o = 16; o; o >>= 1) u2 += __shfl_down_sync(0xffffffffu, u2, o);
            if (lane == 0) nred2[warp] = u2;
        }
        __syncthreads();  // S3
        if (tid < H_) {
            float rn = rsqrtf(nred2[0] + nred2[1] + nred2[2] + nred2[3]);
            float un = u * rn;
            float fs = (eid > 0) ? un : last_s[tid];
            g_fsrc[(size_t)bt * H_ + tid] = fs;
            entsT[tid][eid] = un;
            last_s[tid] = un;
        }
        if (tid == 0) { dists[eid] = sid; g_sel[bt] = (eid > 0) ? 1 : 0; }
        __syncthreads();  // S4
    }
}

// ---------------- K5: ent_feat + z (fp16) ----------------
// grid 256 CTAs x 8 rows, 128 threads (thread = output column j)
__global__ void k_feat(const float* __restrict__ WTe, const float* __restrict__ WTc) {
    __shared__ __align__(16) float fs[8][H_];
    int row0 = blockIdx.x * 8;
    int j = threadIdx.x;
    for (int i = j; i < 8 * H_; i += 128)
        fs[i >> 7][i & 127] = g_fsrc[(size_t)row0 * H_ + i];
    __syncthreads();
    float acc_e[8], acc_c[8];
#pragma unroll
    for (int r = 0; r < 8; r++) { acc_e[r] = 0.f; acc_c[r] = 0.f; }
    const float4* we4 = reinterpret_cast<const float4*>(WTe + (size_t)j * H_);
    const float4* wc4 = reinterpret_cast<const float4*>(WTc + (size_t)j * H_);
#pragma unroll 4
    for (int k4 = 0; k4 < H_ / 4; k4++) {
        float4 we = __ldg(we4 + k4);
        float4 wc = __ldg(wc4 + k4);
#pragma unroll
        for (int r = 0; r < 8; r++) {
            float4 f = *reinterpret_cast<const float4*>(&fs[r][k4 * 4]);
            acc_e[r] += we.x * f.x + we.y * f.y + we.z * f.z + we.w * f.w;
            acc_c[r] += wc.x * f.x + wc.y * f.y + wc.z * f.z + wc.w * f.w;
        }
    }
    for (int r = 0; r < 8; r++) {
        int bt = row0 + r;
        float feat = g_sel[bt] ? acc_e[r] : acc_c[r];
        float z = g_h[(size_t)bt * H_ + j] + feat;
        g_z16[(size_t)bt * H_ + j] = __float2half(z);
    }
}

// ---------------- K6: logits = z @ Wx^T + bx (fp16 mma, fp32 accum) ----------------
// BM=64 BN=64 K=128 (single K load). 128 threads = 4 warps (2x2), warp tile 32x32.
__global__ void k_logits(const float* __restrict__ bx, float* __restrict__ out) {
    __shared__ __align__(16) __half sA[64][128];
    __shared__ __align__(16) __half sB[64][128];
    int tid = threadIdx.x;
    int m0 = blockIdx.y * 64;
    int n0 = blockIdx.x * 64;
    // load A (z) tile: thread -> row tid/2, 8 chunks of 8 halves
    {
        int r = tid >> 1;
        int cbase = (tid & 1) * 8;
        const uint4* src = reinterpret_cast<const uint4*>(g_z16) + (size_t)(m0 + r) * 16;
#pragma unroll
        for (int i = 0; i < 8; i++) {
            int c = cbase + i;
            uint4 v = src[c];
            *reinterpret_cast<uint4*>(&sA[r][(c ^ (r & 7)) << 3]) = v;
        }
    }
    // load B (Wx) tile with V-edge zero fill
    {
        int r = tid >> 1;
        int cbase = (tid & 1) * 8;
        int v_ = n0 + r;
        const uint4* src = reinterpret_cast<const uint4*>(g_wx16) + (size_t)v_ * 16;
#pragma unroll
        for (int i = 0; i < 8; i++) {
            int c = cbase + i;
            uint4 v;
            if (v_ < V_) v = src[c];
            else { v.x = 0u; v.y = 0u; v.z = 0u; v.w = 0u; }
            *reinterpret_cast<uint4*>(&sB[r][(c ^ (r & 7)) << 3]) = v;
        }
    }
    __syncthreads();

    int lane = tid & 31, warp = tid >> 5;
    int wm = warp >> 1, wn = warp & 1;
    float acc[2][4][4];
#pragma unroll
    for (int mt = 0; mt < 2; mt++)
#pragma unroll
        for (int nt = 0; nt < 4; nt++)
#pragma unroll
            for (int i = 0; i < 4; i++) acc[mt][nt][i] = 0.f;

#pragma unroll
    for (int ks = 0; ks < 8; ks++) {
        uint32_t afrag[2][4];
#pragma unroll
        for (int mt = 0; mt < 2; mt++) {
            int row = wm * 32 + mt * 16 + (lane & 15);
            int chunk = ks * 2 + (lane >> 4);
            unsigned addr = (unsigned)__cvta_generic_to_shared(&sA[row][(chunk ^ (row & 7)) << 3]);
            asm volatile("ldmatrix.sync.aligned.m8n8.x4.shared.b16 {%0,%1,%2,%3}, [%4];"
                         : "=r"(afrag[mt][0]), "=r"(afrag[mt][1]),
                           "=r"(afrag[mt][2]), "=r"(afrag[mt][3]) : "r"(addr));
        }
        uint32_t bfrag[4][2];
#pragma unroll
        for (int nt = 0; nt < 4; nt++) {
            int row = wn * 32 + nt * 8 + (lane & 7);
            int chunk = ks * 2 + ((lane >> 3) & 1);
            unsigned addr = (unsigned)__cvta_generic_to_shared(&sB[row][(chunk ^ (row & 7)) << 3]);
            asm volatile("ldmatrix.sync.aligned.m8n8.x2.shared.b16 {%0,%1}, [%2];"
                         : "=r"(bfrag[nt][0]), "=r"(bfrag[nt][1]) : "r"(addr));
        }
#pragma unroll
        for (int mt = 0; mt < 2; mt++)
#pragma unroll
            for (int nt = 0; nt < 4; nt++) {
                asm volatile(
                    "mma.sync.aligned.m16n8k16.row.col.f32.f16.f16.f32 "
                    "{%0,%1,%2,%3}, {%4,%5,%6,%7}, {%8,%9}, {%0,%1,%2,%3};"
                    : "+f"(acc[mt][nt][0]), "+f"(acc[mt][nt][1]),
                      "+f"(acc[mt][nt][2]), "+f"(acc[mt][nt][3])
                    : "r"(afrag[mt][0]), "r"(afrag[mt][1]),
                      "r"(afrag[mt][2]), "r"(afrag[mt][3]),
                      "r"(bfrag[nt][0]), "r"(bfrag[nt][1]));
            }
    }
    // epilogue: c0,c1 -> row lane/4 cols 2(lane%3)... cols 2*(lane&3)+{0,1}; c2,c3 -> row+8
    int rrow = lane >> 2, col = (lane & 3) * 2;
#pragma unroll
    for (int mt = 0; mt < 2; mt++) {
#pragma unroll
        for (int nt = 0; nt < 4; nt++) {
            size_t gm = (size_t)(m0 + wm * 32 + mt * 16 + rrow);
            int gv = n0 + wn * 32 + nt * 8 + col;
            float* a = acc[mt][nt];
            if (gv < V_) {
                float b0 = bx[gv];
                out[gm * V_ + gv]       = a[0] + b0;
                out[(gm + 8) * V_ + gv] = a[2] + b0;
            }
            if (gv + 1 < V_) {
                float b1 = bx[gv + 1];
                out[gm * V_ + gv + 1]       = a[1] + b1;
                out[(gm + 8) * V_ + gv + 1] = a[3] + b1;
            }
        }
    }
}

// ---------------- launch ----------------
extern "C" void kernel_launch(void* const* d_in, const int* in_sizes, int n_in,
                              void* d_out, int out_size) {
    const int*   tokens = (const int*)d_in[0];
    const int*   eids   = (const int*)d_in[1];
    const int*   sids   = (const int*)d_in[2];
    const float* embed  = (const float*)d_in[3];
    const float* Wih    = (const float*)d_in[4];
    const float* Whh    = (const float*)d_in[5];
    const float* bih    = (const float*)d_in[6];
    const float* bhh    = (const float*)d_in[7];
    const float* Wr     = (const float*)d_in[8];
    const float* br     = (const float*)d_in[9];
    const float* We     = (const float*)d_in[10];
    const float* Wd     = (const float*)d_in[11];
    const float* WTe    = (const float*)d_in[12];
    const float* WTc    = (const float*)d_in[13];
    const float* Wx     = (const float*)d_in[14];
    const float* bx     = (const float*)d_in[15];
    const float* ents0  = (const float*)d_in[16];
    const float* lam    = (const float*)d_in[17];
    float* out = (float*)d_out;

    const size_t OFF_R = (size_t)B_ * T_ * V_;
    const size_t OFF_E = OFF_R + (size_t)B_ * T_;

    __half* wx16;
    cudaGetSymbolAddress((void**)&wx16, g_wx16);  // resolves device pointer; not an alloc

    int nwx = V_ * H_;
    k_cvt<<<(nwx + 255) / 256, 256>>>(Wx, wx16, nwx);
    k_xw<<<dim3(T_ / 16, B_), 512>>>(tokens, embed, Wih, bih, bhh);
    k_lstm<<<B_, 512>>>(Whh, Wr, br, out + OFF_R);
    k_vw<<<(B_ * T_) / 16, 256>>>(We, Wd);
    k_ent<<<B_, 256>>>(eids, sids, ents0, lam, out + OFF_E);
    k_feat<<<(B_ * T_) / 8, 128>>>(WTe, WTc);
    k_logits<<<dim3((V_ + 63) / 64, (B_ * T_) / 64), 128>>>(bx, out);
}

// round 3
// speedup vs baseline: 3.1240x; 3.1240x over previous
#include <cuda_runtime.h>
#include <cuda_fp16.h>
#include <cstdint>
#include <cstddef>

#define B_ 4
#define T_ 512
#define H_ 128
#define D_ 300
#define V_ 50257
#define E_ 64

// ---------------- static device scratch ----------------
__device__ float  g_xw  [B_*T_*4*H_];       // gates pre-activation (x path + biases)
__device__ float  g_h   [B_*T_*H_];         // LSTM hidden states
__device__ float  g_weh [B_*T_*H_];         // We @ h
__device__ float  g_wdh [B_*T_*H_];         // Wd @ h
__device__ float  g_fsrc[B_*T_*H_];         // selected feature source vector
__device__ int    g_sel [B_*T_];            // eid > 0 flag
__device__ __half g_z16 [B_*T_*H_];         // z = h + ent_feat (fp16)
__device__ __half g_wx16[(size_t)V_*H_];    // Wx in fp16
__device__ __half g_whh16[16*512*8];        // Whh fp16, layout [k8][n][j] (j = k%8)

// ---------------- K0: Wx -> fp16 ----------------
__global__ void k_cvt(const float* __restrict__ src, __half* __restrict__ dst, int n) {
    int i = blockIdx.x * blockDim.x + threadIdx.x;
    if (i < n) dst[i] = __float2half(src[i]);
}

// ---------------- K0b: Whh -> fp16 interleaved [k8][n][j] ----------------
__global__ void k_whh(const float* __restrict__ Whh) {
    int t = blockIdx.x * 256 + threadIdx.x;
    if (t >= 16 * 512 * 8) return;
    int k8  = t >> 12;       // / (512*8)
    int rem = t & 4095;
    int n   = rem >> 3;
    int j   = rem & 7;
    g_whh16[t] = __float2half(Whh[n * H_ + k8 * 8 + j]);
}

// ---------------- K1: xw = embed[tok] @ Wih^T + bih + bhh ----------------
__global__ void k_xw(const int* __restrict__ tokens, const float* __restrict__ embed,
                     const float* __restrict__ Wih, const float* __restrict__ bih,
                     const float* __restrict__ bhh) {
    __shared__ __align__(16) float xs[16][D_];
    int b = blockIdx.y, t0 = blockIdx.x * 16, n = threadIdx.x;
    for (int i = n; i < 16 * D_; i += 512) {
        int r = i / D_, d = i - r * D_;
        xs[r][d] = embed[(size_t)tokens[b * T_ + t0 + r] * D_ + d];
    }
    __syncthreads();
    float acc[16];
#pragma unroll
    for (int r = 0; r < 16; r++) acc[r] = 0.f;
    const float4* wr = reinterpret_cast<const float4*>(Wih + (size_t)n * D_);
#pragma unroll 5
    for (int d4 = 0; d4 < D_ / 4; d4++) {
        float4 w = __ldg(wr + d4);
#pragma unroll
        for (int r = 0; r < 16; r++) {
            float4 x = *reinterpret_cast<const float4*>(&xs[r][d4 * 4]);
            acc[r] += w.x * x.x + w.y * x.y + w.z * x.z + w.w * x.w;
        }
    }
    float bb = bih[n] + bhh[n];
    for (int r = 0; r < 16; r++)
        g_xw[((size_t)(b * T_ + t0 + r) << 9) + n] = acc[r] + bb;
}

// ---------------- K2: sequential LSTM, fp16 Whh resident in SMEM ----------------
// one CTA per batch, 512 threads (thread n = gate row n), 128KB dynamic smem
__global__ void k_lstm2(const float* __restrict__ Wr, const float* __restrict__ br,
                        float* __restrict__ out_pr) {
    extern __shared__ __align__(16) uint4 sw4[];   // 16*512 uint4 = 128KB
    __shared__ __align__(16) float hs[H_];
    __shared__ float gsm[4 * H_];
    __shared__ float red[4];
    __shared__ float wrs[H_];
    int b = blockIdx.x, n = threadIdx.x;
    const uint4* gw = reinterpret_cast<const uint4*>(g_whh16);
    for (int i = n; i < 16 * 512; i += 512) sw4[i] = gw[i];
    if (n < H_) { hs[n] = 0.f; wrs[n] = Wr[n]; }
    float c = 0.f;
    __syncthreads();
    const float4* hs4 = reinterpret_cast<const float4*>(hs);
    int lane = n & 31;
    for (int t = 0; t < T_; t++) {
        int bt = b * T_ + t;
        float acc = g_xw[((size_t)bt << 9) + n];
#pragma unroll
        for (int k8 = 0; k8 < 16; k8++) {
            uint4 w = sw4[k8 * 512 + n];          // conflict-free LDS.128
            float4 ha = hs4[2 * k8];              // broadcast
            float4 hb = hs4[2 * k8 + 1];
            float2 f0 = __half22float2(*reinterpret_cast<__half2*>(&w.x));
            float2 f1 = __half22float2(*reinterpret_cast<__half2*>(&w.y));
            float2 f2 = __half22float2(*reinterpret_cast<__half2*>(&w.z));
            float2 f3 = __half22float2(*reinterpret_cast<__half2*>(&w.w));
            acc += f0.x * ha.x + f0.y * ha.y + f1.x * ha.z + f1.y * ha.w
                 + f2.x * hb.x + f2.y * hb.y + f3.x * hb.z + f3.y * hb.w;
        }
        gsm[n] = acc;
        __syncthreads();
        if (n < H_) {
            float gi = gsm[n], gf = gsm[n + 128], gg = gsm[n + 256], go = gsm[n + 384];
            float si = 1.f / (1.f + __expf(-gi));
            float sf = 1.f / (1.f + __expf(-gf));
            float so = 1.f / (1.f + __expf(-go));
            c = sf * c + si * tanhf(gg);
            float h = so * tanhf(c);
            hs[n] = h;
            g_h[(size_t)bt * H_ + n] = h;
            float p = h * wrs[n];
#pragma unroll
            for (int o = 16; o; o >>= 1) p += __shfl_down_sync(0xffffffffu, p, o);
            if (lane == 0) red[n >> 5] = p;
        }
        __syncthreads();
        if (n == 0) {
            float s = red[0] + red[1] + red[2] + red[3] + br[0];
            out_pr[bt] = 1.f / (1.f + __expf(-s));
        }
    }
}

// ---------------- K3: veh = We@h, vdh = Wd@h, all (b,t) ----------------
__global__ void k_vw(const float* __restrict__ We, const float* __restrict__ Wd) {
    __shared__ __align__(16) float hsm[16][H_];
    int row0 = blockIdx.x * 16;
    int tid = threadIdx.x;
    for (int i = tid; i < 16 * H_; i += 256)
        hsm[i >> 7][i & 127] = g_h[(size_t)row0 * H_ + i];
    __syncthreads();
    int k = tid & 127;
    const float* M = (tid < 128) ? We : Wd;
    float* O = (tid < 128) ? g_weh : g_wdh;
    const float4* mrow = reinterpret_cast<const float4*>(M + (size_t)k * H_);
    float acc[16];
#pragma unroll
    for (int r = 0; r < 16; r++) acc[r] = 0.f;
#pragma unroll 4
    for (int k4 = 0; k4 < H_ / 4; k4++) {
        float4 w = __ldg(mrow + k4);
#pragma unroll
        for (int r = 0; r < 16; r++) {
            float4 h = *reinterpret_cast<const float4*>(&hsm[r][k4 * 4]);
            acc[r] += w.x * h.x + w.y * h.y + w.z * h.z + w.w * h.w;
        }
    }
    for (int r = 0; r < 16; r++)
        O[(size_t)(row0 + r) * H_ + k] = acc[r];
}

// ---------------- K4: sequential entity recurrence, one CTA per batch ----------------
__global__ void k_ent(const int* __restrict__ eids, const int* __restrict__ sids,
                      const float* __restrict__ ents0, const float* __restrict__ lamp,
                      float* __restrict__ out_pe) {
    __shared__ float entsT[H_][E_ + 1];   // transposed + padded: conflict-free
    __shared__ float dists[E_];
    __shared__ float veh_s[H_], vdh_s[H_], h_s[H_], last_s[H_];
    __shared__ float red2[256];
    __shared__ float nred[4];
    __shared__ float nred2[4];
    int b = blockIdx.x, tid = threadIdx.x;
    float lam = *lamp;
    for (int i = tid; i < E_ * H_; i += 256) {
        int e = i >> 7, j = i & 127;
        entsT[j][e] = ents0[(size_t)(b * E_ + e) * H_ + j];
    }
    if (tid < E_) dists[tid] = 0.f;
    if (tid < H_) last_s[tid] = ents0[(size_t)b * E_ * H_ + tid];
    __syncthreads();
    int q = tid >> 6, e = tid & 63;
    int lane = tid & 31, warp = tid >> 5;
    for (int t = 0; t < T_; t++) {
        int bt = b * T_ + t;
        if (tid < H_) {
            veh_s[tid] = g_weh[(size_t)bt * H_ + tid];
            vdh_s[tid] = g_wdh[(size_t)bt * H_ + tid];
            h_s[tid]   = g_h[(size_t)bt * H_ + tid];
        }
        int eid = eids[bt];
        float sid = (float)sids[bt];
        __syncthreads();
        float p = 0.f;
#pragma unroll
        for (int jj = 0; jj < 32; jj++) {
            int j = q * 32 + jj;
            p += entsT[j][e] * veh_s[j];
        }
        red2[tid] = p;
        float dd = 0.f;
        if (tid < H_) dd = entsT[tid][eid] * vdh_s[tid];
#pragma unroll
        for (int o = 16; o; o >>= 1) dd += __shfl_down_sync(0xffffffffu, dd, o);
        if (tid < H_ && lane == 0) nred[warp] = dd;
        __syncthreads();
        if (tid < E_) {
            float pe = red2[tid] + red2[tid + 64] + red2[tid + 128] + red2[tid + 192]
                     + expf((dists[tid] - sid) * lam);
            out_pe[(size_t)bt * E_ + tid] = pe;
        }
        float delta = 1.f / (1.f + __expf(-(nred[0] + nred[1] + nred[2] + nred[3])));
        float u = 0.f;
        if (tid < H_) {
            u = delta * entsT[tid][eid] + (1.f - delta) * h_s[tid];
            float u2 = u * u;
#pragma unroll
            for (int o = 16; o; o >>= 1) u2 += __shfl_down_sync(0xffffffffu, u2, o);
            if (lane == 0) nred2[warp] = u2;
        }
        __syncthreads();
        if (tid < H_) {
            float rn = rsqrtf(nred2[0] + nred2[1] + nred2[2] + nred2[3]);
            float un = u * rn;
            float fs = (eid > 0) ? un : last_s[tid];
            g_fsrc[(size_t)bt * H_ + tid] = fs;
            entsT[tid][eid] = un;
            last_s[tid] = un;
        }
        if (tid == 0) { dists[eid] = sid; g_sel[bt] = (eid > 0) ? 1 : 0; }
        __syncthreads();
    }
}

// ---------------- K5: ent_feat + z (fp16) ----------------
__global__ void k_feat(const float* __restrict__ WTe, const float* __restrict__ WTc) {
    __shared__ __align__(16) float fs[8][H_];
    int row0 = blockIdx.x * 8;
    int j = threadIdx.x;
    for (int i = j; i < 8 * H_; i += 128)
        fs[i >> 7][i & 127] = g_fsrc[(size_t)row0 * H_ + i];
    __syncthreads();
    float acc_e[8], acc_c[8];
#pragma unroll
    for (int r = 0; r < 8; r++) { acc_e[r] = 0.f; acc_c[r] = 0.f; }
    const float4* we4 = reinterpret_cast<const float4*>(WTe + (size_t)j * H_);
    const float4* wc4 = reinterpret_cast<const float4*>(WTc + (size_t)j * H_);
#pragma unroll 4
    for (int k4 = 0; k4 < H_ / 4; k4++) {
        float4 we = __ldg(we4 + k4);
        float4 wc = __ldg(wc4 + k4);
#pragma unroll
        for (int r = 0; r < 8; r++) {
            float4 f = *reinterpret_cast<const float4*>(&fs[r][k4 * 4]);
            acc_e[r] += we.x * f.x + we.y * f.y + we.z * f.z + we.w * f.w;
            acc_c[r] += wc.x * f.x + wc.y * f.y + wc.z * f.z + wc.w * f.w;
        }
    }
    for (int r = 0; r < 8; r++) {
        int bt = row0 + r;
        float feat = g_sel[bt] ? acc_e[r] : acc_c[r];
        float z = g_h[(size_t)bt * H_ + j] + feat;
        g_z16[(size_t)bt * H_ + j] = __float2half(z);
    }
}

// ---------------- K6: logits = z @ Wx^T + bx (fp16 mma, fp32 accum) ----------------
__global__ void k_logits(const float* __restrict__ bx, float* __restrict__ out) {
    __shared__ __align__(16) __half sA[64][128];
    __shared__ __align__(16) __half sB[64][128];
    int tid = threadIdx.x;
    int m0 = blockIdx.y * 64;
    int n0 = blockIdx.x * 64;
    {
        int r = tid >> 1;
        int cbase = (tid & 1) * 8;
        const uint4* src = reinterpret_cast<const uint4*>(g_z16) + (size_t)(m0 + r) * 16;
#pragma unroll
        for (int i = 0; i < 8; i++) {
            int c = cbase + i;
            uint4 v = src[c];
            *reinterpret_cast<uint4*>(&sA[r][(c ^ (r & 7)) << 3]) = v;
        }
    }
    {
        int r = tid >> 1;
        int cbase = (tid & 1) * 8;
        int v_ = n0 + r;
        const uint4* src = reinterpret_cast<const uint4*>(g_wx16) + (size_t)v_ * 16;
#pragma unroll
        for (int i = 0; i < 8; i++) {
            int c = cbase + i;
            uint4 v;
            if (v_ < V_) v = src[c];
            else { v.x = 0u; v.y = 0u; v.z = 0u; v.w = 0u; }
            *reinterpret_cast<uint4*>(&sB[r][(c ^ (r & 7)) << 3]) = v;
        }
    }
    __syncthreads();

    int lane = tid & 31, warp = tid >> 5;
    int wm = warp >> 1, wn = warp & 1;
    float acc[2][4][4];
#pragma unroll
    for (int mt = 0; mt < 2; mt++)
#pragma unroll
        for (int nt = 0; nt < 4; nt++)
#pragma unroll
            for (int i = 0; i < 4; i++) acc[mt][nt][i] = 0.f;

#pragma unroll
    for (int ks = 0; ks < 8; ks++) {
        uint32_t afrag[2][4];
#pragma unroll
        for (int mt = 0; mt < 2; mt++) {
            int row = wm * 32 + mt * 16 + (lane & 15);
            int chunk = ks * 2 + (lane >> 4);
            unsigned addr = (unsigned)__cvta_generic_to_shared(&sA[row][(chunk ^ (row & 7)) << 3]);
            asm volatile("ldmatrix.sync.aligned.m8n8.x4.shared.b16 {%0,%1,%2,%3}, [%4];"
                         : "=r"(afrag[mt][0]), "=r"(afrag[mt][1]),
                           "=r"(afrag[mt][2]), "=r"(afrag[mt][3]) : "r"(addr));
        }
        uint32_t bfrag[4][2];
#pragma unroll
        for (int nt = 0; nt < 4; nt++) {
            int row = wn * 32 + nt * 8 + (lane & 7);
            int chunk = ks * 2 + ((lane >> 3) & 1);
            unsigned addr = (unsigned)__cvta_generic_to_shared(&sB[row][(chunk ^ (row & 7)) << 3]);
            asm volatile("ldmatrix.sync.aligned.m8n8.x2.shared.b16 {%0,%1}, [%2];"
                         : "=r"(bfrag[nt][0]), "=r"(bfrag[nt][1]) : "r"(addr));
        }
#pragma unroll
        for (int mt = 0; mt < 2; mt++)
#pragma unroll
            for (int nt = 0; nt < 4; nt++) {
                asm volatile(
                    "mma.sync.aligned.m16n8k16.row.col.f32.f16.f16.f32 "
                    "{%0,%1,%2,%3}, {%4,%5,%6,%7}, {%8,%9}, {%0,%1,%2,%3};"
                    : "+f"(acc[mt][nt][0]), "+f"(acc[mt][nt][1]),
                      "+f"(acc[mt][nt][2]), "+f"(acc[mt][nt][3])
                    : "r"(afrag[mt][0]), "r"(afrag[mt][1]),
                      "r"(afrag[mt][2]), "r"(afrag[mt][3]),
                      "r"(bfrag[nt][0]), "r"(bfrag[nt][1]));
            }
    }
    int rrow = lane >> 2, col = (lane & 3) * 2;
#pragma unroll
    for (int mt = 0; mt < 2; mt++) {
#pragma unroll
        for (int nt = 0; nt < 4; nt++) {
            size_t gm = (size_t)(m0 + wm * 32 + mt * 16 + rrow);
            int gv = n0 + wn * 32 + nt * 8 + col;
            float* a = acc[mt][nt];
            if (gv < V_) {
                float b0 = bx[gv];
                out[gm * V_ + gv]       = a[0] + b0;
                out[(gm + 8) * V_ + gv] = a[2] + b0;
            }
            if (gv + 1 < V_) {
                float b1 = bx[gv + 1];
                out[gm * V_ + gv + 1]       = a[1] + b1;
                out[(gm + 8) * V_ + gv + 1] = a[3] + b1;
            }
        }
    }
}

// ---------------- launch ----------------
extern "C" void kernel_launch(void* const* d_in, const int* in_sizes, int n_in,
                              void* d_out, int out_size) {
    const int*   tokens = (const int*)d_in[0];
    const int*   eids   = (const int*)d_in[1];
    const int*   sids   = (const int*)d_in[2];
    const float* embed  = (const float*)d_in[3];
    const float* Wih    = (const float*)d_in[4];
    const float* Whh    = (const float*)d_in[5];
    const float* bih    = (const float*)d_in[6];
    const float* bhh    = (const float*)d_in[7];
    const float* Wr     = (const float*)d_in[8];
    const float* br     = (const float*)d_in[9];
    const float* We     = (const float*)d_in[10];
    const float* Wd     = (const float*)d_in[11];
    const float* WTe    = (const float*)d_in[12];
    const float* WTc    = (const float*)d_in[13];
    const float* Wx     = (const float*)d_in[14];
    const float* bx     = (const float*)d_in[15];
    const float* ents0  = (const float*)d_in[16];
    const float* lam    = (const float*)d_in[17];
    float* out = (float*)d_out;

    const size_t OFF_R = (size_t)B_ * T_ * V_;
    const size_t OFF_E = OFF_R + (size_t)B_ * T_;

    __half* wx16;
    cudaGetSymbolAddress((void**)&wx16, g_wx16);

    static int smem_set = 0;
    if (!smem_set) {
        cudaFuncSetAttribute(k_lstm2, cudaFuncAttributeMaxDynamicSharedMemorySize, 131072);
        smem_set = 1;
    }

    int nwx = V_ * H_;
    k_cvt<<<(nwx + 255) / 256, 256>>>(Wx, wx16, nwx);
    k_whh<<<(16 * 512 * 8 + 255) / 256, 256>>>(Whh);
    k_xw<<<dim3(T_ / 16, B_), 512>>>(tokens, embed, Wih, bih, bhh);
    k_lstm2<<<B_, 512, 131072>>>(Wr, br, out + OFF_R);
    k_vw<<<(B_ * T_) / 16, 256>>>(We, Wd);
    k_ent<<<B_, 256>>>(eids, sids, ents0, lam, out + OFF_E);
    k_feat<<<(B_ * T_) / 8, 128>>>(WTe, WTc);
    k_logits<<<dim3((V_ + 63) / 64, (B_ * T_) / 64), 128>>>(bx, out);
}

// round 4
// speedup vs baseline: 4.0869x; 1.3082x over previous
#include <cuda_runtime.h>
#include <cuda_fp16.h>
#include <cstdint>
#include <cstddef>

#define B_ 4
#define T_ 512
#define H_ 128
#define D_ 300
#define V_ 50257
#define E_ 64

// ---------------- static device scratch ----------------
__device__ float  g_xw  [B_*T_*4*H_];       // gates pre-activation (x path + biases)
__device__ float  g_h   [B_*T_*H_];         // LSTM hidden states
__device__ float  g_weh [B_*T_*H_];         // We @ h
__device__ float  g_wdh [B_*T_*H_];         // Wd @ h
__device__ float  g_fsrc[B_*T_*H_];         // selected feature source vector
__device__ int    g_sel [B_*T_];            // eid > 0 flag
__device__ __half g_z16 [B_*T_*H_];         // z = h + ent_feat (fp16)
__device__ __half g_wx16[(size_t)V_*H_];    // Wx in fp16

__device__ __forceinline__ uint32_t pack_h2(float a, float b) {
    __half2 h = __floats2half2_rn(a, b);
    return *reinterpret_cast<uint32_t*>(&h);
}

// ---------------- K0: Wx -> fp16 ----------------
__global__ void k_cvt(const float* __restrict__ src, __half* __restrict__ dst, int n) {
    int i = blockIdx.x * blockDim.x + threadIdx.x;
    if (i < n) dst[i] = __float2half(src[i]);
}

// ---------------- K1: xw = embed[tok] @ Wih^T + bih + bhh ----------------
__global__ void k_xw(const int* __restrict__ tokens, const float* __restrict__ embed,
                     const float* __restrict__ Wih, const float* __restrict__ bih,
                     const float* __restrict__ bhh) {
    __shared__ __align__(16) float xs[16][D_];
    int b = blockIdx.y, t0 = blockIdx.x * 16, n = threadIdx.x;
    for (int i = n; i < 16 * D_; i += 512) {
        int r = i / D_, d = i - r * D_;
        xs[r][d] = embed[(size_t)tokens[b * T_ + t0 + r] * D_ + d];
    }
    __syncthreads();
    float acc[16];
#pragma unroll
    for (int r = 0; r < 16; r++) acc[r] = 0.f;
    const float4* wr = reinterpret_cast<const float4*>(Wih + (size_t)n * D_);
#pragma unroll 5
    for (int d4 = 0; d4 < D_ / 4; d4++) {
        float4 w = __ldg(wr + d4);
#pragma unroll
        for (int r = 0; r < 16; r++) {
            float4 x = *reinterpret_cast<const float4*>(&xs[r][d4 * 4]);
            acc[r] += w.x * x.x + w.y * x.y + w.z * x.z + w.w * x.w;
        }
    }
    float bb = bih[n] + bhh[n];
    for (int r = 0; r < 16; r++)
        g_xw[((size_t)(b * T_ + t0 + r) << 9) + n] = acc[r] + bb;
}

// ---------------- K2: sequential LSTM, 4 batches packed in N dim, HMMA ----------------
// ONE CTA, 512 threads = 16 warps. Warp w owns gate rows [32w, 32w+32) as two m16
// tiles. Whh lives in registers as A fragments. B frag = h (fp16) for 4 batches
// replicated over n (cols 0..3 = batches, 4..7 dupes).
__global__ void __launch_bounds__(512, 1) k_lstm3(const float* __restrict__ Whh,
                                                  const float* __restrict__ Wr,
                                                  const float* __restrict__ br,
                                                  float* __restrict__ out_pr) {
    __shared__ __half2 hs16[4][72];    // h per batch (64 used, padded: bank-spread)
    __shared__ float gsm[4][520];      // gates per batch (512 used, padded)
    __shared__ float red[16];
    __shared__ float wrs[H_];
    int tid = threadIdx.x, wid = tid >> 5, lane = tid & 31;

    // ---- load Whh into A fragments (once) ----
    uint32_t afr[2][8][4];
    int rbase = wid * 32;
#pragma unroll
    for (int m = 0; m < 2; m++)
#pragma unroll
        for (int ks = 0; ks < 8; ks++) {
            int r0 = rbase + 16 * m + (lane >> 2);
            int k0 = 16 * ks + (lane & 3) * 2;
            const float* w0 = Whh + (size_t)r0 * H_ + k0;
            const float* w1 = Whh + (size_t)(r0 + 8) * H_ + k0;
            float2 aw0 = __ldg(reinterpret_cast<const float2*>(w0));
            float2 aw1 = __ldg(reinterpret_cast<const float2*>(w1));
            float2 aw2 = __ldg(reinterpret_cast<const float2*>(w0 + 8));
            float2 aw3 = __ldg(reinterpret_cast<const float2*>(w1 + 8));
            afr[m][ks][0] = pack_h2(aw0.x, aw0.y);
            afr[m][ks][1] = pack_h2(aw1.x, aw1.y);
            afr[m][ks][2] = pack_h2(aw2.x, aw2.y);
            afr[m][ks][3] = pack_h2(aw3.x, aw3.y);
        }

    // ---- init state ----
    if (tid < 4 * 72) reinterpret_cast<__half2*>(hs16)[tid] = __half2half2(__float2half(0.f));
    if (tid < H_) wrs[tid] = Wr[tid];
    float c = 0.f;                       // cell state: thread (b = tid>>7, r = tid&127)
    int myb = tid >> 7, myr = tid & 127;
    float brv = br[0];
    __syncthreads();

    int kq = lane & 3;              // k quad
    int bb = (lane >> 2) & 3;       // batch for B frag (cols 4..7 duplicate 0..3)
    int ecol = (lane & 3) * 2;      // accumulator column pair base
    bool ewr = (lane & 3) < 2;      // lanes holding batches 0..3
    int erow = rbase + (lane >> 2);

    for (int t = 0; t < T_; t++) {
        // prefetch xw for this step (consumed after mma phase)
        size_t xwb = ((size_t)(myb * T_ + t) << 9) + myr;
        float x0 = __ldg(&g_xw[xwb]);
        float x1 = __ldg(&g_xw[xwb + 128]);
        float x2 = __ldg(&g_xw[xwb + 256]);
        float x3 = __ldg(&g_xw[xwb + 384]);

        float acc0[4] = {0.f, 0.f, 0.f, 0.f};
        float acc1[4] = {0.f, 0.f, 0.f, 0.f};
#pragma unroll
        for (int ks = 0; ks < 8; ks++) {
            uint32_t b0 = *reinterpret_cast<const uint32_t*>(&hs16[bb][ks * 8 + kq]);
            uint32_t b1 = *reinterpret_cast<const uint32_t*>(&hs16[bb][ks * 8 + kq + 4]);
            asm volatile(
                "mma.sync.aligned.m16n8k16.row.col.f32.f16.f16.f32 "
                "{%0,%1,%2,%3}, {%4,%5,%6,%7}, {%8,%9}, {%0,%1,%2,%3};"
                : "+f"(acc0[0]), "+f"(acc0[1]), "+f"(acc0[2]), "+f"(acc0[3])
                : "r"(afr[0][ks][0]), "r"(afr[0][ks][1]),
                  "r"(afr[0][ks][2]), "r"(afr[0][ks][3]),
                  "r"(b0), "r"(b1));
            asm volatile(
                "mma.sync.aligned.m16n8k16.row.col.f32.f16.f16.f32 "
                "{%0,%1,%2,%3}, {%4,%5,%6,%7}, {%8,%9}, {%0,%1,%2,%3};"
                : "+f"(acc1[0]), "+f"(acc1[1]), "+f"(acc1[2]), "+f"(acc1[3])
                : "r"(afr[1][ks][0]), "r"(afr[1][ks][1]),
                  "r"(afr[1][ks][2]), "r"(afr[1][ks][3]),
                  "r"(b0), "r"(b1));
        }
        if (ewr) {
            gsm[ecol    ][erow     ] = acc0[0];
            gsm[ecol + 1][erow     ] = acc0[1];
            gsm[ecol    ][erow + 8 ] = acc0[2];
            gsm[ecol + 1][erow + 8 ] = acc0[3];
            gsm[ecol    ][erow + 16] = acc1[0];
            gsm[ecol + 1][erow + 16] = acc1[1];
            gsm[ecol    ][erow + 24] = acc1[2];
            gsm[ecol + 1][erow + 24] = acc1[3];
        }
        __syncthreads();   // gates visible

        // nonlinearity: thread owns (myb, myr)
        float gi = gsm[myb][myr]       + x0;
        float gf = gsm[myb][myr + 128] + x1;
        float gg = gsm[myb][myr + 256] + x2;
        float go = gsm[myb][myr + 384] + x3;
        float si = 1.f / (1.f + __expf(-gi));
        float sf = 1.f / (1.f + __expf(-gf));
        float so = 1.f / (1.f + __expf(-go));
        c = sf * c + si * tanhf(gg);
        float h = so * tanhf(c);
        g_h[(size_t)(myb * T_ + t) * H_ + myr] = h;
        reinterpret_cast<__half*>(&hs16[myb][0])[myr] = __float2half(h);
        float p = h * wrs[myr];
#pragma unroll
        for (int o = 16; o; o >>= 1) p += __shfl_down_sync(0xffffffffu, p, o);
        if (lane == 0) red[wid] = p;
        __syncthreads();   // h + partials visible

        if (tid < 4) {
            float s = red[tid * 4] + red[tid * 4 + 1] + red[tid * 4 + 2] + red[tid * 4 + 3] + brv;
            out_pr[tid * T_ + t] = 1.f / (1.f + __expf(-s));
        }
    }
}

// ---------------- K3: veh = We@h, vdh = Wd@h, all (b,t) ----------------
__global__ void k_vw(const float* __restrict__ We, const float* __restrict__ Wd) {
    __shared__ __align__(16) float hsm[16][H_];
    int row0 = blockIdx.x * 16;
    int tid = threadIdx.x;
    for (int i = tid; i < 16 * H_; i += 256)
        hsm[i >> 7][i & 127] = g_h[(size_t)row0 * H_ + i];
    __syncthreads();
    int k = tid & 127;
    const float* M = (tid < 128) ? We : Wd;
    float* O = (tid < 128) ? g_weh : g_wdh;
    const float4* mrow = reinterpret_cast<const float4*>(M + (size_t)k * H_);
    float acc[16];
#pragma unroll
    for (int r = 0; r < 16; r++) acc[r] = 0.f;
#pragma unroll 4
    for (int k4 = 0; k4 < H_ / 4; k4++) {
        float4 w = __ldg(mrow + k4);
#pragma unroll
        for (int r = 0; r < 16; r++) {
            float4 h = *reinterpret_cast<const float4*>(&hsm[r][k4 * 4]);
            acc[r] += w.x * h.x + w.y * h.y + w.z * h.z + w.w * h.w;
        }
    }
    for (int r = 0; r < 16; r++)
        O[(size_t)(row0 + r) * H_ + k] = acc[r];
}

// ---------------- K4: sequential entity recurrence, one CTA per batch ----------------
__global__ void k_ent(const int* __restrict__ eids, const int* __restrict__ sids,
                      const float* __restrict__ ents0, const float* __restrict__ lamp,
                      float* __restrict__ out_pe) {
    __shared__ float entsT[H_][E_ + 1];
    __shared__ float dists[E_];
    __shared__ float veh_s[H_], vdh_s[H_], h_s[H_], last_s[H_];
    __shared__ float red2[256];
    __shared__ float nred[4];
    __shared__ float nred2[4];
    int b = blockIdx.x, tid = threadIdx.x;
    float lam = *lamp;
    for (int i = tid; i < E_ * H_; i += 256) {
        int e = i >> 7, j = i & 127;
        entsT[j][e] = ents0[(size_t)(b * E_ + e) * H_ + j];
    }
    if (tid < E_) dists[tid] = 0.f;
    if (tid < H_) last_s[tid] = ents0[(size_t)b * E_ * H_ + tid];
    __syncthreads();
    int q = tid >> 6, e = tid & 63;
    int lane = tid & 31, warp = tid >> 5;

    // prefetch t=0
    float pv = 0.f, pd = 0.f, ph = 0.f;
    {
        size_t bt0 = (size_t)b * T_ * H_;
        if (tid < H_) {
            pv = __ldg(&g_weh[bt0 + tid]);
            pd = __ldg(&g_wdh[bt0 + tid]);
            ph = __ldg(&g_h[bt0 + tid]);
        }
    }
    int peid = __ldg(&eids[b * T_]);
    float psid = (float)__ldg(&sids[b * T_]);

    for (int t = 0; t < T_; t++) {
        int bt = b * T_ + t;
        if (tid < H_) { veh_s[tid] = pv; vdh_s[tid] = pd; h_s[tid] = ph; }
        int eid = peid;
        float sid = psid;
        __syncthreads();  // S1
        // prefetch t+1 (latency hidden behind this step's compute)
        if (t + 1 < T_) {
            size_t bt1 = (size_t)(bt + 1) * H_;
            if (tid < H_) {
                pv = __ldg(&g_weh[bt1 + tid]);
                pd = __ldg(&g_wdh[bt1 + tid]);
                ph = __ldg(&g_h[bt1 + tid]);
            }
            peid = __ldg(&eids[bt + 1]);
            psid = (float)__ldg(&sids[bt + 1]);
        }
        float p = 0.f;
#pragma unroll
        for (int jj = 0; jj < 32; jj++) {
            int j = q * 32 + jj;
            p += entsT[j][e] * veh_s[j];
        }
        red2[tid] = p;
        float dd = 0.f;
        if (tid < H_) dd = entsT[tid][eid] * vdh_s[tid];
#pragma unroll
        for (int o = 16; o; o >>= 1) dd += __shfl_down_sync(0xffffffffu, dd, o);
        if (tid < H_ && lane == 0) nred[warp] = dd;
        __syncthreads();  // S2
        if (tid < E_) {
            float pe = red2[tid] + red2[tid + 64] + red2[tid + 128] + red2[tid + 192]
                     + expf((dists[tid] - sid) * lam);
            out_pe[(size_t)bt * E_ + tid] = pe;
        }
        float delta = 1.f / (1.f + __expf(-(nred[0] + nred[1] + nred[2] + nred[3])));
        float u = 0.f;
        if (tid < H_) {
            u = delta * entsT[tid][eid] + (1.f - delta) * h_s[tid];
            float u2 = u * u;
#pragma unroll
            for (int o = 16; o; o >>= 1) u2 += __shfl_down_sync(0xffffffffu, u2, o);
            if (lane == 0) nred2[warp] = u2;
        }
        __syncthreads();  // S3
        if (tid < H_) {
            float rn = rsqrtf(nred2[0] + nred2[1] + nred2[2] + nred2[3]);
            float un = u * rn;
            float fs = (eid > 0) ? un : last_s[tid];
            g_fsrc[(size_t)bt * H_ + tid] = fs;
            entsT[tid][eid] = un;
            last_s[tid] = un;
        }
        if (tid == 0) { dists[eid] = sid; g_sel[bt] = (eid > 0) ? 1 : 0; }
        __syncthreads();  // S4
    }
}

// ---------------- K5: ent_feat + z (fp16) ----------------
__global__ void k_feat(const float* __restrict__ WTe, const float* __restrict__ WTc) {
    __shared__ __align__(16) float fs[8][H_];
    int row0 = blockIdx.x * 8;
    int j = threadIdx.x;
    for (int i = j; i < 8 * H_; i += 128)
        fs[i >> 7][i & 127] = g_fsrc[(size_t)row0 * H_ + i];
    __syncthreads();
    float acc_e[8], acc_c[8];
#pragma unroll
    for (int r = 0; r < 8; r++) { acc_e[r] = 0.f; acc_c[r] = 0.f; }
    const float4* we4 = reinterpret_cast<const float4*>(WTe + (size_t)j * H_);
    const float4* wc4 = reinterpret_cast<const float4*>(WTc + (size_t)j * H_);
#pragma unroll 4
    for (int k4 = 0; k4 < H_ / 4; k4++) {
        float4 we = __ldg(we4 + k4);
        float4 wc = __ldg(wc4 + k4);
#pragma unroll
        for (int r = 0; r < 8; r++) {
            float4 f = *reinterpret_cast<const float4*>(&fs[r][k4 * 4]);
            acc_e[r] += we.x * f.x + we.y * f.y + we.z * f.z + we.w * f.w;
            acc_c[r] += wc.x * f.x + wc.y * f.y + wc.z * f.z + wc.w * f.w;
        }
    }
    for (int r = 0; r < 8; r++) {
        int bt = row0 + r;
        float feat = g_sel[bt] ? acc_e[r] : acc_c[r];
        float z = g_h[(size_t)bt * H_ + j] + feat;
        g_z16[(size_t)bt * H_ + j] = __float2half(z);
    }
}

// ---------------- K6: logits = z @ Wx^T + bx (fp16 mma, fp32 accum) ----------------
__global__ void k_logits(const float* __restrict__ bx, float* __restrict__ out) {
    __shared__ __align__(16) __half sA[64][128];
    __shared__ __align__(16) __half sB[64][128];
    int tid = threadIdx.x;
    int m0 = blockIdx.y * 64;
    int n0 = blockIdx.x * 64;
    {
        int r = tid >> 1;
        int cbase = (tid & 1) * 8;
        const uint4* src = reinterpret_cast<const uint4*>(g_z16) + (size_t)(m0 + r) * 16;
#pragma unroll
        for (int i = 0; i < 8; i++) {
            int c = cbase + i;
            uint4 v = src[c];
            *reinterpret_cast<uint4*>(&sA[r][(c ^ (r & 7)) << 3]) = v;
        }
    }
    {
        int r = tid >> 1;
        int cbase = (tid & 1) * 8;
        int v_ = n0 + r;
        const uint4* src = reinterpret_cast<const uint4*>(g_wx16) + (size_t)v_ * 16;
#pragma unroll
        for (int i = 0; i < 8; i++) {
            int c = cbase + i;
            uint4 v;
            if (v_ < V_) v = src[c];
            else { v.x = 0u; v.y = 0u; v.z = 0u; v.w = 0u; }
            *reinterpret_cast<uint4*>(&sB[r][(c ^ (r & 7)) << 3]) = v;
        }
    }
    __syncthreads();

    int lane = tid & 31, warp = tid >> 5;
    int wm = warp >> 1, wn = warp & 1;
    float acc[2][4][4];
#pragma unroll
    for (int mt = 0; mt < 2; mt++)
#pragma unroll
        for (int nt = 0; nt < 4; nt++)
#pragma unroll
            for (int i = 0; i < 4; i++) acc[mt][nt][i] = 0.f;

#pragma unroll
    for (int ks = 0; ks < 8; ks++) {
        uint32_t afrag[2][4];
#pragma unroll
        for (int mt = 0; mt < 2; mt++) {
            int row = wm * 32 + mt * 16 + (lane & 15);
            int chunk = ks * 2 + (lane >> 4);
            unsigned addr = (unsigned)__cvta_generic_to_shared(&sA[row][(chunk ^ (row & 7)) << 3]);
            asm volatile("ldmatrix.sync.aligned.m8n8.x4.shared.b16 {%0,%1,%2,%3}, [%4];"
                         : "=r"(afrag[mt][0]), "=r"(afrag[mt][1]),
                           "=r"(afrag[mt][2]), "=r"(afrag[mt][3]) : "r"(addr));
        }
        uint32_t bfrag[4][2];
#pragma unroll
        for (int nt = 0; nt < 4; nt++) {
            int row = wn * 32 + nt * 8 + (lane & 7);
            int chunk = ks * 2 + ((lane >> 3) & 1);
            unsigned addr = (unsigned)__cvta_generic_to_shared(&sB[row][(chunk ^ (row & 7)) << 3]);
            asm volatile("ldmatrix.sync.aligned.m8n8.x2.shared.b16 {%0,%1}, [%2];"
                         : "=r"(bfrag[nt][0]), "=r"(bfrag[nt][1]) : "r"(addr));
        }
#pragma unroll
        for (int mt = 0; mt < 2; mt++)
#pragma unroll
            for (int nt = 0; nt < 4; nt++) {
                asm volatile(
                    "mma.sync.aligned.m16n8k16.row.col.f32.f16.f16.f32 "
                    "{%0,%1,%2,%3}, {%4,%5,%6,%7}, {%8,%9}, {%0,%1,%2,%3};"
                    : "+f"(acc[mt][nt][0]), "+f"(acc[mt][nt][1]),
                      "+f"(acc[mt][nt][2]), "+f"(acc[mt][nt][3])
                    : "r"(afrag[mt][0]), "r"(afrag[mt][1]),
                      "r"(afrag[mt][2]), "r"(afrag[mt][3]),
                      "r"(bfrag[nt][0]), "r"(bfrag[nt][1]));
            }
    }
    int rrow = lane >> 2, col = (lane & 3) * 2;
#pragma unroll
    for (int mt = 0; mt < 2; mt++) {
#pragma unroll
        for (int nt = 0; nt < 4; nt++) {
            size_t gm = (size_t)(m0 + wm * 32 + mt * 16 + rrow);
            int gv = n0 + wn * 32 + nt * 8 + col;
            float* a = acc[mt][nt];
            if (gv < V_) {
                float b0 = bx[gv];
                out[gm * V_ + gv]       = a[0] + b0;
                out[(gm + 8) * V_ + gv] = a[2] + b0;
            }
            if (gv + 1 < V_) {
                float b1 = bx[gv + 1];
                out[gm * V_ + gv + 1]       = a[1] + b1;
                out[(gm + 8) * V_ + gv + 1] = a[3] + b1;
            }
        }
    }
}

// ---------------- launch ----------------
extern "C" void kernel_launch(void* const* d_in, const int* in_sizes, int n_in,
                              void* d_out, int out_size) {
    const int*   tokens = (const int*)d_in[0];
    const int*   eids   = (const int*)d_in[1];
    const int*   sids   = (const int*)d_in[2];
    const float* embed  = (const float*)d_in[3];
    const float* Wih    = (const float*)d_in[4];
    const float* Whh    = (const float*)d_in[5];
    const float* bih    = (const float*)d_in[6];
    const float* bhh    = (const float*)d_in[7];
    const float* Wr     = (const float*)d_in[8];
    const float* br     = (const float*)d_in[9];
    const float* We     = (const float*)d_in[10];
    const float* Wd     = (const float*)d_in[11];
    const float* WTe    = (const float*)d_in[12];
    const float* WTc    = (const float*)d_in[13];
    const float* Wx     = (const float*)d_in[14];
    const float* bx     = (const float*)d_in[15];
    const float* ents0  = (const float*)d_in[16];
    const float* lam    = (const float*)d_in[17];
    float* out = (float*)d_out;

    const size_t OFF_R = (size_t)B_ * T_ * V_;
    const size_t OFF_E = OFF_R + (size_t)B_ * T_;

    __half* wx16;
    cudaGetSymbolAddress((void**)&wx16, g_wx16);

    int nwx = V_ * H_;
    k_cvt<<<(nwx + 255) / 256, 256>>>(Wx, wx16, nwx);
    k_xw<<<dim3(T_ / 16, B_), 512>>>(tokens, embed, Wih, bih, bhh);
    k_lstm3<<<1, 512>>>(Whh, Wr, br, out + OFF_R);
    k_vw<<<(B_ * T_) / 16, 256>>>(We, Wd);
    k_ent<<<B_, 256>>>(eids, sids, ents0, lam, out + OFF_E);
    k_feat<<<(B_ * T_) / 8, 128>>>(WTe, WTc);
    k_logits<<<dim3((V_ + 63) / 64, (B_ * T_) / 64), 128>>>(bx, out);
}

// round 5
// speedup vs baseline: 4.8370x; 1.1835x over previous
#include <cuda_runtime.h>
#include <cuda_fp16.h>
#include <cstdint>
#include <cstddef>

#define B_ 4
#define T_ 512
#define H_ 128
#define D_ 300
#define V_ 50257
#define E_ 64

// ---------------- static device scratch ----------------
__device__ float  g_xw  [B_*T_*4*H_];       // gates pre-activation (x path + biases)
__device__ float  g_h   [B_*T_*H_];         // LSTM hidden states
__device__ float  g_weh [B_*T_*H_];         // We @ h
__device__ float  g_wdh [B_*T_*H_];         // Wd @ h
__device__ float  g_fsrc[B_*T_*H_];         // selected feature source vector
__device__ int    g_sel [B_*T_];            // eid > 0 flag
__device__ __half g_z16 [B_*T_*H_];         // z = h + ent_feat (fp16)
__device__ __half g_wx16[(size_t)V_*H_];    // Wx in fp16

__device__ __forceinline__ uint32_t pack_h2(float a, float b) {
    __half2 h = __floats2half2_rn(a, b);
    return *reinterpret_cast<uint32_t*>(&h);
}

// ---------------- K0: Wx -> fp16 ----------------
__global__ void k_cvt(const float* __restrict__ src, __half* __restrict__ dst, int n) {
    int i = blockIdx.x * blockDim.x + threadIdx.x;
    if (i < n) dst[i] = __float2half(src[i]);
}

// ---------------- K1: xw = embed[tok] @ Wih^T + bih + bhh ----------------
__global__ void k_xw(const int* __restrict__ tokens, const float* __restrict__ embed,
                     const float* __restrict__ Wih, const float* __restrict__ bih,
                     const float* __restrict__ bhh) {
    __shared__ __align__(16) float xs[16][D_];
    int b = blockIdx.y, t0 = blockIdx.x * 16, n = threadIdx.x;
    for (int i = n; i < 16 * D_; i += 512) {
        int r = i / D_, d = i - r * D_;
        xs[r][d] = embed[(size_t)tokens[b * T_ + t0 + r] * D_ + d];
    }
    __syncthreads();
    float acc[16];
#pragma unroll
    for (int r = 0; r < 16; r++) acc[r] = 0.f;
    const float4* wr = reinterpret_cast<const float4*>(Wih + (size_t)n * D_);
#pragma unroll 5
    for (int d4 = 0; d4 < D_ / 4; d4++) {
        float4 w = __ldg(wr + d4);
#pragma unroll
        for (int r = 0; r < 16; r++) {
            float4 x = *reinterpret_cast<const float4*>(&xs[r][d4 * 4]);
            acc[r] += w.x * x.x + w.y * x.y + w.z * x.z + w.w * x.w;
        }
    }
    float bb = bih[n] + bhh[n];
    for (int r = 0; r < 16; r++)
        g_xw[((size_t)(b * T_ + t0 + r) << 9) + n] = acc[r] + bb;
}

// ---------------- K2: sequential LSTM, 4 batches packed in N dim, HMMA ----------------
// ONE CTA, 512 threads = 16 warps. Whh in registers as A fragments. xw prefetched
// one step ahead (latency fully hidden). pred_r moved out (computed in k_vw).
__global__ void __launch_bounds__(512, 1) k_lstm3(const float* __restrict__ Whh) {
    __shared__ __half2 hs16[4][72];
    __shared__ float gsm[4][520];
    int tid = threadIdx.x, wid = tid >> 5, lane = tid & 31;

    // ---- load Whh into A fragments (once) ----
    uint32_t afr[2][8][4];
    int rbase = wid * 32;
#pragma unroll
    for (int m = 0; m < 2; m++)
#pragma unroll
        for (int ks = 0; ks < 8; ks++) {
            int r0 = rbase + 16 * m + (lane >> 2);
            int k0 = 16 * ks + (lane & 3) * 2;
            const float* w0 = Whh + (size_t)r0 * H_ + k0;
            const float* w1 = Whh + (size_t)(r0 + 8) * H_ + k0;
            float2 aw0 = __ldg(reinterpret_cast<const float2*>(w0));
            float2 aw1 = __ldg(reinterpret_cast<const float2*>(w1));
            float2 aw2 = __ldg(reinterpret_cast<const float2*>(w0 + 8));
            float2 aw3 = __ldg(reinterpret_cast<const float2*>(w1 + 8));
            afr[m][ks][0] = pack_h2(aw0.x, aw0.y);
            afr[m][ks][1] = pack_h2(aw1.x, aw1.y);
            afr[m][ks][2] = pack_h2(aw2.x, aw2.y);
            afr[m][ks][3] = pack_h2(aw3.x, aw3.y);
        }

    if (tid < 4 * 72) reinterpret_cast<__half2*>(hs16)[tid] = __half2half2(__float2half(0.f));
    float c = 0.f;
    int myb = tid >> 7, myr = tid & 127;
    __syncthreads();

    int kq = lane & 3;
    int bb = (lane >> 2) & 3;
    int ecol = (lane & 3) * 2;
    bool ewr = (lane & 3) < 2;
    int erow = rbase + (lane >> 2);

    // prefetch xw for t=0
    size_t xwb0 = ((size_t)(myb * T_) << 9) + myr;
    float xa0 = __ldg(&g_xw[xwb0]);
    float xa1 = __ldg(&g_xw[xwb0 + 128]);
    float xa2 = __ldg(&g_xw[xwb0 + 256]);
    float xa3 = __ldg(&g_xw[xwb0 + 384]);

    for (int t = 0; t < T_; t++) {
        float acc0[4] = {0.f, 0.f, 0.f, 0.f};
        float acc1[4] = {0.f, 0.f, 0.f, 0.f};
#pragma unroll
        for (int ks = 0; ks < 8; ks++) {
            uint32_t b0 = *reinterpret_cast<const uint32_t*>(&hs16[bb][ks * 8 + kq]);
            uint32_t b1 = *reinterpret_cast<const uint32_t*>(&hs16[bb][ks * 8 + kq + 4]);
            asm volatile(
                "mma.sync.aligned.m16n8k16.row.col.f32.f16.f16.f32 "
                "{%0,%1,%2,%3}, {%4,%5,%6,%7}, {%8,%9}, {%0,%1,%2,%3};"
                : "+f"(acc0[0]), "+f"(acc0[1]), "+f"(acc0[2]), "+f"(acc0[3])
                : "r"(afr[0][ks][0]), "r"(afr[0][ks][1]),
                  "r"(afr[0][ks][2]), "r"(afr[0][ks][3]),
                  "r"(b0), "r"(b1));
            asm volatile(
                "mma.sync.aligned.m16n8k16.row.col.f32.f16.f16.f32 "
                "{%0,%1,%2,%3}, {%4,%5,%6,%7}, {%8,%9}, {%0,%1,%2,%3};"
                : "+f"(acc1[0]), "+f"(acc1[1]), "+f"(acc1[2]), "+f"(acc1[3])
                : "r"(afr[1][ks][0]), "r"(afr[1][ks][1]),
                  "r"(afr[1][ks][2]), "r"(afr[1][ks][3]),
                  "r"(b0), "r"(b1));
        }
        // prefetch xw for t+1 (consumed next iteration -> latency hidden)
        float xb0 = 0.f, xb1 = 0.f, xb2 = 0.f, xb3 = 0.f;
        if (t + 1 < T_) {
            size_t xwb = ((size_t)(myb * T_ + t + 1) << 9) + myr;
            xb0 = __ldg(&g_xw[xwb]);
            xb1 = __ldg(&g_xw[xwb + 128]);
            xb2 = __ldg(&g_xw[xwb + 256]);
            xb3 = __ldg(&g_xw[xwb + 384]);
        }
        if (ewr) {
            gsm[ecol    ][erow     ] = acc0[0];
            gsm[ecol + 1][erow     ] = acc0[1];
            gsm[ecol    ][erow + 8 ] = acc0[2];
            gsm[ecol + 1][erow + 8 ] = acc0[3];
            gsm[ecol    ][erow + 16] = acc1[0];
            gsm[ecol + 1][erow + 16] = acc1[1];
            gsm[ecol    ][erow + 24] = acc1[2];
            gsm[ecol + 1][erow + 24] = acc1[3];
        }
        __syncthreads();   // gates visible

        float gi = gsm[myb][myr]       + xa0;
        float gf = gsm[myb][myr + 128] + xa1;
        float gg = gsm[myb][myr + 256] + xa2;
        float go = gsm[myb][myr + 384] + xa3;
        float si = 1.f / (1.f + __expf(-gi));
        float sf = 1.f / (1.f + __expf(-gf));
        float so = 1.f / (1.f + __expf(-go));
        c = sf * c + si * tanhf(gg);
        float h = so * tanhf(c);
        g_h[(size_t)(myb * T_ + t) * H_ + myr] = h;
        reinterpret_cast<__half*>(&hs16[myb][0])[myr] = __float2half(h);
        __syncthreads();   // h visible for next mma

        xa0 = xb0; xa1 = xb1; xa2 = xb2; xa3 = xb3;
    }
}

// ---------------- K3: veh = We@h, vdh = Wd@h, + pred_r ----------------
__global__ void k_vw(const float* __restrict__ We, const float* __restrict__ Wd,
                     const float* __restrict__ Wr, const float* __restrict__ br,
                     float* __restrict__ out_pr) {
    __shared__ __align__(16) float hsm[16][H_];
    __shared__ float wr_s[H_];
    int row0 = blockIdx.x * 16;
    int tid = threadIdx.x;
    for (int i = tid; i < 16 * H_; i += 256)
        hsm[i >> 7][i & 127] = g_h[(size_t)row0 * H_ + i];
    if (tid < H_) wr_s[tid] = Wr[tid];
    __syncthreads();
    int k = tid & 127;
    const float* M = (tid < 128) ? We : Wd;
    float* O = (tid < 128) ? g_weh : g_wdh;
    const float4* mrow = reinterpret_cast<const float4*>(M + (size_t)k * H_);
    float acc[16];
#pragma unroll
    for (int r = 0; r < 16; r++) acc[r] = 0.f;
#pragma unroll 4
    for (int k4 = 0; k4 < H_ / 4; k4++) {
        float4 w = __ldg(mrow + k4);
#pragma unroll
        for (int r = 0; r < 16; r++) {
            float4 h = *reinterpret_cast<const float4*>(&hsm[r][k4 * 4]);
            acc[r] += w.x * h.x + w.y * h.y + w.z * h.z + w.w * h.w;
        }
    }
    for (int r = 0; r < 16; r++)
        O[(size_t)(row0 + r) * H_ + k] = acc[r];

    // pred_r epilogue: warp w handles rows 2w, 2w+1
    int warp = tid >> 5, lane = tid & 31;
    float brv = __ldg(br);
#pragma unroll
    for (int rr = 0; rr < 2; rr++) {
        int r = warp * 2 + rr;
        float p = hsm[r][lane]      * wr_s[lane]
                + hsm[r][lane + 32] * wr_s[lane + 32]
                + hsm[r][lane + 64] * wr_s[lane + 64]
                + hsm[r][lane + 96] * wr_s[lane + 96];
#pragma unroll
        for (int o = 16; o; o >>= 1) p += __shfl_down_sync(0xffffffffu, p, o);
        if (lane == 0) out_pr[row0 + r] = 1.f / (1.f + __expf(-(p + brv)));
    }
}

// ---------------- K4: sequential entity recurrence, one CTA per batch ----------------
__global__ void k_ent(const int* __restrict__ eids, const int* __restrict__ sids,
                      const float* __restrict__ ents0, const float* __restrict__ lamp,
                      float* __restrict__ out_pe) {
    __shared__ float entsT[H_][E_ + 1];
    __shared__ float dists[E_];
    __shared__ float veh_s[H_], vdh_s[H_], h_s[H_], last_s[H_];
    __shared__ float red2[256];
    __shared__ float nred[4];
    __shared__ float nred2[4];
    int b = blockIdx.x, tid = threadIdx.x;
    float lam = *lamp;
    for (int i = tid; i < E_ * H_; i += 256) {
        int e = i >> 7, j = i & 127;
        entsT[j][e] = ents0[(size_t)(b * E_ + e) * H_ + j];
    }
    if (tid < E_) dists[tid] = 0.f;
    if (tid < H_) last_s[tid] = ents0[(size_t)b * E_ * H_ + tid];
    __syncthreads();
    int q = tid >> 6, e = tid & 63;
    int lane = tid & 31, warp = tid >> 5;

    float pv = 0.f, pd = 0.f, ph = 0.f;
    {
        size_t bt0 = (size_t)b * T_ * H_;
        if (tid < H_) {
            pv = __ldg(&g_weh[bt0 + tid]);
            pd = __ldg(&g_wdh[bt0 + tid]);
            ph = __ldg(&g_h[bt0 + tid]);
        }
    }
    int peid = __ldg(&eids[b * T_]);
    float psid = (float)__ldg(&sids[b * T_]);

    for (int t = 0; t < T_; t++) {
        int bt = b * T_ + t;
        if (tid < H_) { veh_s[tid] = pv; vdh_s[tid] = pd; h_s[tid] = ph; }
        int eid = peid;
        float sid = psid;
        __syncthreads();  // S1: staging + prev-step entsT/dists writes visible
        if (t + 1 < T_) {
            size_t bt1 = (size_t)(bt + 1) * H_;
            if (tid < H_) {
                pv = __ldg(&g_weh[bt1 + tid]);
                pd = __ldg(&g_wdh[bt1 + tid]);
                ph = __ldg(&g_h[bt1 + tid]);
            }
            peid = __ldg(&eids[bt + 1]);
            psid = (float)__ldg(&sids[bt + 1]);
        }
        float p = 0.f;
#pragma unroll
        for (int jj = 0; jj < 32; jj++) {
            int j = q * 32 + jj;
            p += entsT[j][e] * veh_s[j];
        }
        red2[tid] = p;
        float dd = 0.f;
        if (tid < H_) dd = entsT[tid][eid] * vdh_s[tid];
#pragma unroll
        for (int o = 16; o; o >>= 1) dd += __shfl_down_sync(0xffffffffu, dd, o);
        if (tid < H_ && lane == 0) nred[warp] = dd;
        __syncthreads();  // S2
        if (tid < E_) {
            float pe = red2[tid] + red2[tid + 64] + red2[tid + 128] + red2[tid + 192]
                     + expf((dists[tid] - sid) * lam);
            out_pe[(size_t)bt * E_ + tid] = pe;
        }
        float delta = 1.f / (1.f + __expf(-(nred[0] + nred[1] + nred[2] + nred[3])));
        float u = 0.f;
        if (tid < H_) {
            u = delta * entsT[tid][eid] + (1.f - delta) * h_s[tid];
            float u2 = u * u;
#pragma unroll
            for (int o = 16; o; o >>= 1) u2 += __shfl_down_sync(0xffffffffu, u2, o);
            if (lane == 0) nred2[warp] = u2;
        }
        __syncthreads();  // S3
        if (tid < H_) {
            float rn = rsqrtf(nred2[0] + nred2[1] + nred2[2] + nred2[3]);
            float un = u * rn;
            float fs = (eid > 0) ? un : last_s[tid];
            g_fsrc[(size_t)bt * H_ + tid] = fs;
            entsT[tid][eid] = un;
            last_s[tid] = un;
        }
        if (tid == 0) { dists[eid] = sid; g_sel[bt] = (eid > 0) ? 1 : 0; }
        // no S4: next iteration's S1 orders these writes before the next reads
    }
}

// ---------------- K5: ent_feat + z (fp16) ----------------
__global__ void k_feat(const float* __restrict__ WTe, const float* __restrict__ WTc) {
    __shared__ __align__(16) float fs[8][H_];
    int row0 = blockIdx.x * 8;
    int j = threadIdx.x;
    for (int i = j; i < 8 * H_; i += 128)
        fs[i >> 7][i & 127] = g_fsrc[(size_t)row0 * H_ + i];
    __syncthreads();
    float acc_e[8], acc_c[8];
#pragma unroll
    for (int r = 0; r < 8; r++) { acc_e[r] = 0.f; acc_c[r] = 0.f; }
    const float4* we4 = reinterpret_cast<const float4*>(WTe + (size_t)j * H_);
    const float4* wc4 = reinterpret_cast<const float4*>(WTc + (size_t)j * H_);
#pragma unroll 4
    for (int k4 = 0; k4 < H_ / 4; k4++) {
        float4 we = __ldg(we4 + k4);
        float4 wc = __ldg(wc4 + k4);
#pragma unroll
        for (int r = 0; r < 8; r++) {
            float4 f = *reinterpret_cast<const float4*>(&fs[r][k4 * 4]);
            acc_e[r] += we.x * f.x + we.y * f.y + we.z * f.z + we.w * f.w;
            acc_c[r] += wc.x * f.x + wc.y * f.y + wc.z * f.z + wc.w * f.w;
        }
    }
    for (int r = 0; r < 8; r++) {
        int bt = row0 + r;
        float feat = g_sel[bt] ? acc_e[r] : acc_c[r];
        float z = g_h[(size_t)bt * H_ + j] + feat;
        g_z16[(size_t)bt * H_ + j] = __float2half(z);
    }
}

// ---------------- K6: logits = z @ Wx^T + bx, 128x128 tiles ----------------
__global__ void __launch_bounds__(256, 2) k_logits(const float* __restrict__ bx,
                                                   float* __restrict__ out) {
    extern __shared__ __align__(16) __half smemh[];
    __half (*sA)[128] = reinterpret_cast<__half (*)[128]>(smemh);
    __half (*sB)[128] = reinterpret_cast<__half (*)[128]>(smemh + 128 * 128);
    int tid = threadIdx.x;
    int m0 = blockIdx.y * 128;
    int n0 = blockIdx.x * 128;
    {
        int r = tid >> 1;
        int cbase = (tid & 1) * 8;
        const uint4* src = reinterpret_cast<const uint4*>(g_z16) + (size_t)(m0 + r) * 16;
#pragma unroll
        for (int i = 0; i < 8; i++) {
            int c = cbase + i;
            uint4 v = src[c];
            *reinterpret_cast<uint4*>(&sA[r][(c ^ (r & 7)) << 3]) = v;
        }
    }
    {
        int r = tid >> 1;
        int cbase = (tid & 1) * 8;
        int v_ = n0 + r;
        const uint4* src = reinterpret_cast<const uint4*>(g_wx16) + (size_t)v_ * 16;
#pragma unroll
        for (int i = 0; i < 8; i++) {
            int c = cbase + i;
            uint4 v;
            if (v_ < V_) v = src[c];
            else { v.x = 0u; v.y = 0u; v.z = 0u; v.w = 0u; }
            *reinterpret_cast<uint4*>(&sB[r][(c ^ (r & 7)) << 3]) = v;
        }
    }
    __syncthreads();

    int lane = tid & 31, warp = tid >> 5;
    int wm = warp >> 1, wn = warp & 1;      // 4 m-warps x 2 n-warps
    float acc[2][8][4];
#pragma unroll
    for (int mt = 0; mt < 2; mt++)
#pragma unroll
        for (int nt = 0; nt < 8; nt++)
#pragma unroll
            for (int i = 0; i < 4; i++) acc[mt][nt][i] = 0.f;

#pragma unroll
    for (int ks = 0; ks < 8; ks++) {
        uint32_t afrag[2][4];
#pragma unroll
        for (int mt = 0; mt < 2; mt++) {
            int row = wm * 32 + mt * 16 + (lane & 15);
            int chunk = ks * 2 + (lane >> 4);
            unsigned addr = (unsigned)__cvta_generic_to_shared(&sA[row][(chunk ^ (row & 7)) << 3]);
            asm volatile("ldmatrix.sync.aligned.m8n8.x4.shared.b16 {%0,%1,%2,%3}, [%4];"
                         : "=r"(afrag[mt][0]), "=r"(afrag[mt][1]),
                           "=r"(afrag[mt][2]), "=r"(afrag[mt][3]) : "r"(addr));
        }
        uint32_t bfrag[8][2];
#pragma unroll
        for (int nt = 0; nt < 8; nt++) {
            int row = wn * 64 + nt * 8 + (lane & 7);
            int chunk = ks * 2 + ((lane >> 3) & 1);
            unsigned addr = (unsigned)__cvta_generic_to_shared(&sB[row][(chunk ^ (row & 7)) << 3]);
            asm volatile("ldmatrix.sync.aligned.m8n8.x2.shared.b16 {%0,%1}, [%2];"
                         : "=r"(bfrag[nt][0]), "=r"(bfrag[nt][1]) : "r"(addr));
        }
#pragma unroll
        for (int mt = 0; mt < 2; mt++)
#pragma unroll
            for (int nt = 0; nt < 8; nt++) {
                asm volatile(
                    "mma.sync.aligned.m16n8k16.row.col.f32.f16.f16.f32 "
                    "{%0,%1,%2,%3}, {%4,%5,%6,%7}, {%8,%9}, {%0,%1,%2,%3};"
                    : "+f"(acc[mt][nt][0]), "+f"(acc[mt][nt][1]),
                      "+f"(acc[mt][nt][2]), "+f"(acc[mt][nt][3])
                    : "r"(afrag[mt][0]), "r"(afrag[mt][1]),
                      "r"(afrag[mt][2]), "r"(afrag[mt][3]),
                      "r"(bfrag[nt][0]), "r"(bfrag[nt][1]));
            }
    }
    int rrow = lane >> 2, col = (lane & 3) * 2;
#pragma unroll
    for (int mt = 0; mt < 2; mt++) {
#pragma unroll
        for (int nt = 0; nt < 8; nt++) {
            size_t gm = (size_t)(m0 + wm * 32 + mt * 16 + rrow);
            int gv = n0 + wn * 64 + nt * 8 + col;
            float* a = acc[mt][nt];
            if (gv < V_) {
                float b0 = bx[gv];
                out[gm * V_ + gv]       = a[0] + b0;
                out[(gm + 8) * V_ + gv] = a[2] + b0;
            }
            if (gv + 1 < V_) {
                float b1 = bx[gv + 1];
                out[gm * V_ + gv + 1]       = a[1] + b1;
                out[(gm + 8) * V_ + gv + 1] = a[3] + b1;
            }
        }
    }
}

// ---------------- launch ----------------
extern "C" void kernel_launch(void* const* d_in, const int* in_sizes, int n_in,
                              void* d_out, int out_size) {
    const int*   tokens = (const int*)d_in[0];
    const int*   eids   = (const int*)d_in[1];
    const int*   sids   = (const int*)d_in[2];
    const float* embed  = (const float*)d_in[3];
    const float* Wih    = (const float*)d_in[4];
    const float* Whh    = (const float*)d_in[5];
    const float* bih    = (const float*)d_in[6];
    const float* bhh    = (const float*)d_in[7];
    const float* Wr     = (const float*)d_in[8];
    const float* br     = (const float*)d_in[9];
    const float* We     = (const float*)d_in[10];
    const float* Wd     = (const float*)d_in[11];
    const float* WTe    = (const float*)d_in[12];
    const float* WTc    = (const float*)d_in[13];
    const float* Wx     = (const float*)d_in[14];
    const float* bx     = (const float*)d_in[15];
    const float* ents0  = (const float*)d_in[16];
    const float* lam    = (const float*)d_in[17];
    float* out = (float*)d_out;

    const size_t OFF_R = (size_t)B_ * T_ * V_;
    const size_t OFF_E = OFF_R + (size_t)B_ * T_;

    __half* wx16;
    cudaGetSymbolAddress((void**)&wx16, g_wx16);

    static int attr_set = 0;
    if (!attr_set) {
        cudaFuncSetAttribute(k_logits, cudaFuncAttributeMaxDynamicSharedMemorySize, 65536);
        attr_set = 1;
    }

    int nwx = V_ * H_;
    k_cvt<<<(nwx + 255) / 256, 256>>>(Wx, wx16, nwx);
    k_xw<<<dim3(T_ / 16, B_), 512>>>(tokens, embed, Wih, bih, bhh);
    k_lstm3<<<1, 512>>>(Whh);
    k_vw<<<(B_ * T_) / 16, 256>>>(We, Wd, Wr, br, out + OFF_R);
    k_ent<<<B_, 256>>>(eids, sids, ents0, lam, out + OFF_E);
    k_feat<<<(B_ * T_) / 8, 128>>>(WTe, WTc);
    k_logits<<<dim3((V_ + 127) / 128, (B_ * T_) / 128), 256, 65536>>>(bx, out);
}

// round 6
// speedup vs baseline: 5.6831x; 1.1749x over previous
#include <cuda_runtime.h>
#include <cuda_fp16.h>
#include <cstdint>
#include <cstddef>

#define B_ 4
#define T_ 512
#define H_ 128
#define D_ 300
#define V_ 50257
#define E_ 64

// ---------------- static device scratch ----------------
__device__ float  g_xwp [T_*H_*16];         // gates pre-act, layout [t][dim][batch][gate]
__device__ float  g_h   [B_*T_*H_];         // LSTM hidden states
__device__ float  g_weh [B_*T_*H_];         // We @ h
__device__ float  g_wdh [B_*T_*H_];         // Wd @ h
__device__ float  g_fsrc[B_*T_*H_];         // selected feature source vector
__device__ int    g_sel [B_*T_];            // eid > 0 flag
__device__ __half g_z16 [B_*T_*H_];         // z = h + ent_feat (fp16)
__device__ __half g_wx16[(size_t)V_*H_];    // Wx in fp16

__device__ __forceinline__ uint32_t pack_h2(float a, float b) {
    __half2 h = __floats2half2_rn(a, b);
    return *reinterpret_cast<uint32_t*>(&h);
}
__device__ __forceinline__ float tanh_fast(float x) {
    float y;
    asm("tanh.approx.f32 %0, %1;" : "=f"(y) : "f"(x));
    return y;
}
__device__ __forceinline__ float sigmoid_fast(float x) {
    return 0.5f * tanh_fast(0.5f * x) + 0.5f;
}

// ---------------- K0: Wx -> fp16 ----------------
__global__ void k_cvt(const float* __restrict__ src, __half* __restrict__ dst, int n) {
    int i = blockIdx.x * blockDim.x + threadIdx.x;
    if (i < n) dst[i] = __float2half(src[i]);
}

// ---------------- K1: xw = embed[tok] @ Wih^T + bih + bhh, permuted layout ----------------
__global__ void k_xw(const int* __restrict__ tokens, const float* __restrict__ embed,
                     const float* __restrict__ Wih, const float* __restrict__ bih,
                     const float* __restrict__ bhh) {
    __shared__ __align__(16) float xs[16][D_];
    int b = blockIdx.y, t0 = blockIdx.x * 16, n = threadIdx.x;
    for (int i = n; i < 16 * D_; i += 512) {
        int r = i / D_, d = i - r * D_;
        xs[r][d] = embed[(size_t)tokens[b * T_ + t0 + r] * D_ + d];
    }
    __syncthreads();
    float acc[16];
#pragma unroll
    for (int r = 0; r < 16; r++) acc[r] = 0.f;
    const float4* wr = reinterpret_cast<const float4*>(Wih + (size_t)n * D_);
#pragma unroll 5
    for (int d4 = 0; d4 < D_ / 4; d4++) {
        float4 w = __ldg(wr + d4);
#pragma unroll
        for (int r = 0; r < 16; r++) {
            float4 x = *reinterpret_cast<const float4*>(&xs[r][d4 * 4]);
            acc[r] += w.x * x.x + w.y * x.y + w.z * x.z + w.w * x.w;
        }
    }
    float bb = bih[n] + bhh[n];
    int gate = n >> 7, dd = n & 127;
    for (int r = 0; r < 16; r++)
        g_xwp[(((size_t)(t0 + r) * H_ + dd) << 4) + b * 4 + gate] = acc[r] + bb;
}

// ---------------- K2: sequential LSTM, gate-permuted, 1 barrier/step ----------------
// 16 warps; warp w owns h-dims [8w,8w+8). Tile0 rows = {i,f} x dims, tile1 = {g,o}.
// All 32 lanes do nonlinearity for exactly one (dim,batch) pair in registers.
__global__ void __launch_bounds__(512, 1) k_lstm4(const float* __restrict__ Whh) {
    __shared__ __half2 hbuf[2][4][72];   // double-buffered h (fp16), per batch
    int tid = threadIdx.x, wid = tid >> 5, lane = tid & 31;

    // ---- load Whh into permuted A fragments (once) ----
    uint32_t afr[2][8][4];
#pragma unroll
    for (int m = 0; m < 2; m++)
#pragma unroll
        for (int ks = 0; ks < 8; ks++) {
            int rl = (m ? 256 : 0) + 8 * wid + (lane >> 2);   // i or g row
            int rh = rl + 128;                                // f or o row
            int k0 = 16 * ks + (lane & 3) * 2;
            float2 wl0 = __ldg(reinterpret_cast<const float2*>(Whh + (size_t)rl * H_ + k0));
            float2 wh0 = __ldg(reinterpret_cast<const float2*>(Whh + (size_t)rh * H_ + k0));
            float2 wl8 = __ldg(reinterpret_cast<const float2*>(Whh + (size_t)rl * H_ + k0 + 8));
            float2 wh8 = __ldg(reinterpret_cast<const float2*>(Whh + (size_t)rh * H_ + k0 + 8));
            afr[m][ks][0] = pack_h2(wl0.x, wl0.y);
            afr[m][ks][1] = pack_h2(wh0.x, wh0.y);
            afr[m][ks][2] = pack_h2(wl8.x, wl8.y);
            afr[m][ks][3] = pack_h2(wh8.x, wh8.y);
        }

    if (tid < 288) {
        __half2 z = __half2half2(__float2half(0.f));
        (&hbuf[0][0][0])[tid] = z;
    }
    int bq = lane & 3;
    int hd = 8 * wid + (lane >> 2);            // h-dim owned by this lane
    int myb = ((bq & 1) << 1) | (bq >> 1);     // batch handled in nonlinearity
    int sel = bq >> 1;                         // 0: even acc regs, 1: odd
    int bb = (lane >> 2) & 3;                  // batch for B-frag load
    int kq = lane & 3;
    float c = 0.f;
    __syncthreads();

    const float4* xwp4 = reinterpret_cast<const float4*>(g_xwp);
    float4 xa = __ldg(&xwp4[(size_t)hd * 4 + myb]);   // t=0

    for (int t = 0; t < T_; t++) {
        int buf = t & 1;
        float acc0[4] = {0.f, 0.f, 0.f, 0.f};
        float acc1[4] = {0.f, 0.f, 0.f, 0.f};
#pragma unroll
        for (int ks = 0; ks < 8; ks++) {
            uint32_t b0 = *reinterpret_cast<const uint32_t*>(&hbuf[buf][bb][ks * 8 + kq]);
            uint32_t b1 = *reinterpret_cast<const uint32_t*>(&hbuf[buf][bb][ks * 8 + kq + 4]);
            asm volatile(
                "mma.sync.aligned.m16n8k16.row.col.f32.f16.f16.f32 "
                "{%0,%1,%2,%3}, {%4,%5,%6,%7}, {%8,%9}, {%0,%1,%2,%3};"
                : "+f"(acc0[0]), "+f"(acc0[1]), "+f"(acc0[2]), "+f"(acc0[3])
                : "r"(afr[0][ks][0]), "r"(afr[0][ks][1]),
                  "r"(afr[0][ks][2]), "r"(afr[0][ks][3]),
                  "r"(b0), "r"(b1));
            asm volatile(
                "mma.sync.aligned.m16n8k16.row.col.f32.f16.f16.f32 "
                "{%0,%1,%2,%3}, {%4,%5,%6,%7}, {%8,%9}, {%0,%1,%2,%3};"
                : "+f"(acc1[0]), "+f"(acc1[1]), "+f"(acc1[2]), "+f"(acc1[3])
                : "r"(afr[1][ks][0]), "r"(afr[1][ks][1]),
                  "r"(afr[1][ks][2]), "r"(afr[1][ks][3]),
                  "r"(b0), "r"(b1));
        }
        // prefetch next step's xw (hidden behind nonlinearity + barrier)
        float4 xn = make_float4(0.f, 0.f, 0.f, 0.f);
        if (t + 1 < T_)
            xn = __ldg(&xwp4[((size_t)(t + 1) * H_ + hd) * 4 + myb]);

        float gi = (sel ? acc0[1] : acc0[0]) + xa.x;
        float gf = (sel ? acc0[3] : acc0[2]) + xa.y;
        float gg = (sel ? acc1[1] : acc1[0]) + xa.z;
        float go = (sel ? acc1[3] : acc1[2]) + xa.w;
        float si = sigmoid_fast(gi);
        float sf = sigmoid_fast(gf);
        float so = sigmoid_fast(go);
        c = sf * c + si * tanh_fast(gg);
        float h = so * tanh_fast(c);
        g_h[(size_t)(myb * T_ + t) * H_ + hd] = h;
        reinterpret_cast<__half*>(&hbuf[buf ^ 1][myb][0])[hd] = __float2half(h);
        __syncthreads();
        xa = xn;
    }
}

// ---------------- K3: veh = We@h, vdh = Wd@h, + pred_r ----------------
__global__ void k_vw(const float* __restrict__ We, const float* __restrict__ Wd,
                     const float* __restrict__ Wr, const float* __restrict__ br,
                     float* __restrict__ out_pr) {
    __shared__ __align__(16) float hsm[16][H_];
    __shared__ float wr_s[H_];
    int row0 = blockIdx.x * 16;
    int tid = threadIdx.x;
    for (int i = tid; i < 16 * H_; i += 256)
        hsm[i >> 7][i & 127] = g_h[(size_t)row0 * H_ + i];
    if (tid < H_) wr_s[tid] = Wr[tid];
    __syncthreads();
    int k = tid & 127;
    const float* M = (tid < 128) ? We : Wd;
    float* O = (tid < 128) ? g_weh : g_wdh;
    const float4* mrow = reinterpret_cast<const float4*>(M + (size_t)k * H_);
    float acc[16];
#pragma unroll
    for (int r = 0; r < 16; r++) acc[r] = 0.f;
#pragma unroll 4
    for (int k4 = 0; k4 < H_ / 4; k4++) {
        float4 w = __ldg(mrow + k4);
#pragma unroll
        for (int r = 0; r < 16; r++) {
            float4 h = *reinterpret_cast<const float4*>(&hsm[r][k4 * 4]);
            acc[r] += w.x * h.x + w.y * h.y + w.z * h.z + w.w * h.w;
        }
    }
    for (int r = 0; r < 16; r++)
        O[(size_t)(row0 + r) * H_ + k] = acc[r];

    int warp = tid >> 5, lane = tid & 31;
    float brv = __ldg(br);
#pragma unroll
    for (int rr = 0; rr < 2; rr++) {
        int r = warp * 2 + rr;
        float p = hsm[r][lane]      * wr_s[lane]
                + hsm[r][lane + 32] * wr_s[lane + 32]
                + hsm[r][lane + 64] * wr_s[lane + 64]
                + hsm[r][lane + 96] * wr_s[lane + 96];
#pragma unroll
        for (int o = 16; o; o >>= 1) p += __shfl_down_sync(0xffffffffu, p, o);
        if (lane == 0) out_pr[row0 + r] = 1.f / (1.f + __expf(-(p + brv)));
    }
}

// ---------------- K4: sequential entity recurrence, one CTA per batch ----------------
__global__ void k_ent(const int* __restrict__ eids, const int* __restrict__ sids,
                      const float* __restrict__ ents0, const float* __restrict__ lamp,
                      float* __restrict__ out_pe) {
    __shared__ float entsT[H_][E_ + 1];
    __shared__ float dists[E_];
    __shared__ float veh_s[H_], vdh_s[H_], h_s[H_], last_s[H_];
    __shared__ float red2[256];
    __shared__ float nred[4];
    __shared__ float nred2[4];
    int b = blockIdx.x, tid = threadIdx.x;
    float lam = *lamp;
    for (int i = tid; i < E_ * H_; i += 256) {
        int e = i >> 7, j = i & 127;
        entsT[j][e] = ents0[(size_t)(b * E_ + e) * H_ + j];
    }
    if (tid < E_) dists[tid] = 0.f;
    if (tid < H_) last_s[tid] = ents0[(size_t)b * E_ * H_ + tid];
    __syncthreads();
    int q = tid >> 6, e = tid & 63;
    int lane = tid & 31, warp = tid >> 5;

    float pv = 0.f, pd = 0.f, ph = 0.f;
    {
        size_t bt0 = (size_t)b * T_ * H_;
        if (tid < H_) {
            pv = __ldg(&g_weh[bt0 + tid]);
            pd = __ldg(&g_wdh[bt0 + tid]);
            ph = __ldg(&g_h[bt0 + tid]);
        }
    }
    int peid = __ldg(&eids[b * T_]);
    float psid = (float)__ldg(&sids[b * T_]);

    for (int t = 0; t < T_; t++) {
        int bt = b * T_ + t;
        if (tid < H_) { veh_s[tid] = pv; vdh_s[tid] = pd; h_s[tid] = ph; }
        int eid = peid;
        float sid = psid;
        __syncthreads();  // S1
        if (t + 1 < T_) {
            size_t bt1 = (size_t)(bt + 1) * H_;
            if (tid < H_) {
                pv = __ldg(&g_weh[bt1 + tid]);
                pd = __ldg(&g_wdh[bt1 + tid]);
                ph = __ldg(&g_h[bt1 + tid]);
            }
            peid = __ldg(&eids[bt + 1]);
            psid = (float)__ldg(&sids[bt + 1]);
        }
        float p = 0.f;
#pragma unroll
        for (int jj = 0; jj < 32; jj++) {
            int j = q * 32 + jj;
            p += entsT[j][e] * veh_s[j];
        }
        red2[tid] = p;
        float dd = 0.f;
        if (tid < H_) dd = entsT[tid][eid] * vdh_s[tid];
#pragma unroll
        for (int o = 16; o; o >>= 1) dd += __shfl_down_sync(0xffffffffu, dd, o);
        if (tid < H_ && lane == 0) nred[warp] = dd;
        __syncthreads();  // S2
        if (tid < E_) {
            float pe = red2[tid] + red2[tid + 64] + red2[tid + 128] + red2[tid + 192]
                     + expf((dists[tid] - sid) * lam);
            out_pe[(size_t)bt * E_ + tid] = pe;
        }
        float delta = 1.f / (1.f + __expf(-(nred[0] + nred[1] + nred[2] + nred[3])));
        float u = 0.f;
        if (tid < H_) {
            u = delta * entsT[tid][eid] + (1.f - delta) * h_s[tid];
            float u2 = u * u;
#pragma unroll
            for (int o = 16; o; o >>= 1) u2 += __shfl_down_sync(0xffffffffu, u2, o);
            if (lane == 0) nred2[warp] = u2;
        }
        __syncthreads();  // S3
        if (tid < H_) {
            float rn = rsqrtf(nred2[0] + nred2[1] + nred2[2] + nred2[3]);
            float un = u * rn;
            float fs = (eid > 0) ? un : last_s[tid];
            g_fsrc[(size_t)bt * H_ + tid] = fs;
            entsT[tid][eid] = un;
            last_s[tid] = un;
        }
        if (tid == 0) { dists[eid] = sid; g_sel[bt] = (eid > 0) ? 1 : 0; }
        // next iteration's S1 orders these writes before the next reads
    }
}

// ---------------- K5: ent_feat + z (fp16) ----------------
__global__ void k_feat(const float* __restrict__ WTe, const float* __restrict__ WTc) {
    __shared__ __align__(16) float fs[8][H_];
    int row0 = blockIdx.x * 8;
    int j = threadIdx.x;
    for (int i = j; i < 8 * H_; i += 128)
        fs[i >> 7][i & 127] = g_fsrc[(size_t)row0 * H_ + i];
    __syncthreads();
    float acc_e[8], acc_c[8];
#pragma unroll
    for (int r = 0; r < 8; r++) { acc_e[r] = 0.f; acc_c[r] = 0.f; }
    const float4* we4 = reinterpret_cast<const float4*>(WTe + (size_t)j * H_);
    const float4* wc4 = reinterpret_cast<const float4*>(WTc + (size_t)j * H_);
#pragma unroll 4
    for (int k4 = 0; k4 < H_ / 4; k4++) {
        float4 we = __ldg(we4 + k4);
        float4 wc = __ldg(wc4 + k4);
#pragma unroll
        for (int r = 0; r < 8; r++) {
            float4 f = *reinterpret_cast<const float4*>(&fs[r][k4 * 4]);
            acc_e[r] += we.x * f.x + we.y * f.y + we.z * f.z + we.w * f.w;
            acc_c[r] += wc.x * f.x + wc.y * f.y + wc.z * f.z + wc.w * f.w;
        }
    }
    for (int r = 0; r < 8; r++) {
        int bt = row0 + r;
        float feat = g_sel[bt] ? acc_e[r] : acc_c[r];
        float z = g_h[(size_t)bt * H_ + j] + feat;
        g_z16[(size_t)bt * H_ + j] = __float2half(z);
    }
}

// ---------------- K6: logits = z @ Wx^T + bx, 128x128 tiles ----------------
__global__ void __launch_bounds__(256, 2) k_logits(const float* __restrict__ bx,
                                                   float* __restrict__ out) {
    extern __shared__ __align__(16) __half smemh[];
    __half (*sA)[128] = reinterpret_cast<__half (*)[128]>(smemh);
    __half (*sB)[128] = reinterpret_cast<__half (*)[128]>(smemh + 128 * 128);
    int tid = threadIdx.x;
    int m0 = blockIdx.y * 128;
    int n0 = blockIdx.x * 128;
    {
        int r = tid >> 1;
        int cbase = (tid & 1) * 8;
        const uint4* src = reinterpret_cast<const uint4*>(g_z16) + (size_t)(m0 + r) * 16;
#pragma unroll
        for (int i = 0; i < 8; i++) {
            int c = cbase + i;
            uint4 v = src[c];
            *reinterpret_cast<uint4*>(&sA[r][(c ^ (r & 7)) << 3]) = v;
        }
    }
    {
        int r = tid >> 1;
        int cbase = (tid & 1) * 8;
        int v_ = n0 + r;
        const uint4* src = reinterpret_cast<const uint4*>(g_wx16) + (size_t)v_ * 16;
#pragma unroll
        for (int i = 0; i < 8; i++) {
            int c = cbase + i;
            uint4 v;
            if (v_ < V_) v = src[c];
            else { v.x = 0u; v.y = 0u; v.z = 0u; v.w = 0u; }
            *reinterpret_cast<uint4*>(&sB[r][(c ^ (r & 7)) << 3]) = v;
        }
    }
    __syncthreads();

    int lane = tid & 31, warp = tid >> 5;
    int wm = warp >> 1, wn = warp & 1;
    float acc[2][8][4];
#pragma unroll
    for (int mt = 0; mt < 2; mt++)
#pragma unroll
        for (int nt = 0; nt < 8; nt++)
#pragma unroll
            for (int i = 0; i < 4; i++) acc[mt][nt][i] = 0.f;

#pragma unroll
    for (int ks = 0; ks < 8; ks++) {
        uint32_t afrag[2][4];
#pragma unroll
        for (int mt = 0; mt < 2; mt++) {
            int row = wm * 32 + mt * 16 + (lane & 15);
            int chunk = ks * 2 + (lane >> 4);
            unsigned addr = (unsigned)__cvta_generic_to_shared(&sA[row][(chunk ^ (row & 7)) << 3]);
            asm volatile("ldmatrix.sync.aligned.m8n8.x4.shared.b16 {%0,%1,%2,%3}, [%4];"
                         : "=r"(afrag[mt][0]), "=r"(afrag[mt][1]),
                           "=r"(afrag[mt][2]), "=r"(afrag[mt][3]) : "r"(addr));
        }
        uint32_t bfrag[8][2];
#pragma unroll
        for (int nt = 0; nt < 8; nt++) {
            int row = wn * 64 + nt * 8 + (lane & 7);
            int chunk = ks * 2 + ((lane >> 3) & 1);
            unsigned addr = (unsigned)__cvta_generic_to_shared(&sB[row][(chunk ^ (row & 7)) << 3]);
            asm volatile("ldmatrix.sync.aligned.m8n8.x2.shared.b16 {%0,%1}, [%2];"
                         : "=r"(bfrag[nt][0]), "=r"(bfrag[nt][1]) : "r"(addr));
        }
#pragma unroll
        for (int mt = 0; mt < 2; mt++)
#pragma unroll
            for (int nt = 0; nt < 8; nt++) {
                asm volatile(
                    "mma.sync.aligned.m16n8k16.row.col.f32.f16.f16.f32 "
                    "{%0,%1,%2,%3}, {%4,%5,%6,%7}, {%8,%9}, {%0,%1,%2,%3};"
                    : "+f"(acc[mt][nt][0]), "+f"(acc[mt][nt][1]),
                      "+f"(acc[mt][nt][2]), "+f"(acc[mt][nt][3])
                    : "r"(afrag[mt][0]), "r"(afrag[mt][1]),
                      "r"(afrag[mt][2]), "r"(afrag[mt][3]),
                      "r"(bfrag[nt][0]), "r"(bfrag[nt][1]));
            }
    }
    int rrow = lane >> 2, col = (lane & 3) * 2;
#pragma unroll
    for (int mt = 0; mt < 2; mt++) {
#pragma unroll
        for (int nt = 0; nt < 8; nt++) {
            size_t gm = (size_t)(m0 + wm * 32 + mt * 16 + rrow);
            int gv = n0 + wn * 64 + nt * 8 + col;
            float* a = acc[mt][nt];
            if (gv < V_) {
                float b0 = bx[gv];
                out[gm * V_ + gv]       = a[0] + b0;
                out[(gm + 8) * V_ + gv] = a[2] + b0;
            }
            if (gv + 1 < V_) {
                float b1 = bx[gv + 1];
                out[gm * V_ + gv + 1]       = a[1] + b1;
                out[(gm + 8) * V_ + gv + 1] = a[3] + b1;
            }
        }
    }
}

// ---------------- launch ----------------
extern "C" void kernel_launch(void* const* d_in, const int* in_sizes, int n_in,
                              void* d_out, int out_size) {
    const int*   tokens = (const int*)d_in[0];
    const int*   eids   = (const int*)d_in[1];
    const int*   sids   = (const int*)d_in[2];
    const float* embed  = (const float*)d_in[3];
    const float* Wih    = (const float*)d_in[4];
    const float* Whh    = (const float*)d_in[5];
    const float* bih    = (const float*)d_in[6];
    const float* bhh    = (const float*)d_in[7];
    const float* Wr     = (const float*)d_in[8];
    const float* br     = (const float*)d_in[9];
    const float* We     = (const float*)d_in[10];
    const float* Wd     = (const float*)d_in[11];
    const float* WTe    = (const float*)d_in[12];
    const float* WTc    = (const float*)d_in[13];
    const float* Wx     = (const float*)d_in[14];
    const float* bx     = (const float*)d_in[15];
    const float* ents0  = (const float*)d_in[16];
    const float* lam    = (const float*)d_in[17];
    float* out = (float*)d_out;

    const size_t OFF_R = (size_t)B_ * T_ * V_;
    const size_t OFF_E = OFF_R + (size_t)B_ * T_;

    __half* wx16;
    cudaGetSymbolAddress((void**)&wx16, g_wx16);

    static int attr_set = 0;
    if (!attr_set) {
        cudaFuncSetAttribute(k_logits, cudaFuncAttributeMaxDynamicSharedMemorySize, 65536);
        attr_set = 1;
    }

    int nwx = V_ * H_;
    k_cvt<<<(nwx + 255) / 256, 256>>>(Wx, wx16, nwx);
    k_xw<<<dim3(T_ / 16, B_), 512>>>(tokens, embed, Wih, bih, bhh);
    k_lstm4<<<1, 512>>>(Whh);
    k_vw<<<(B_ * T_) / 16, 256>>>(We, Wd, Wr, br, out + OFF_R);
    k_ent<<<B_, 256>>>(eids, sids, ents0, lam, out + OFF_E);
    k_feat<<<(B_ * T_) / 8, 128>>>(WTe, WTc);
    k_logits<<<dim3((V_ + 127) / 128, (B_ * T_) / 128), 256, 65536>>>(bx, out);
}

// round 7
// speedup vs baseline: 5.6973x; 1.0025x over previous
#include <cuda_runtime.h>
#include <cuda_fp16.h>
#include <cstdint>
#include <cstddef>

#define B_ 4
#define T_ 512
#define H_ 128
#define D_ 300
#define V_ 50257
#define E_ 64

// ---------------- static device scratch ----------------
__device__ float  g_xwp [T_*H_*16];         // gates pre-act, layout [t][dim][batch][gate]
__device__ float  g_h   [B_*T_*H_];         // LSTM hidden states
__device__ float  g_weh [B_*T_*H_];         // We @ h
__device__ float  g_wdh [B_*T_*H_];         // Wd @ h
__device__ float  g_hh  [B_*T_];            // ||h||^2
__device__ float  g_fsrc[B_*T_*H_];         // selected feature source vector
__device__ int    g_sel [B_*T_];            // eid > 0 flag
__device__ __half g_z16 [B_*T_*H_];         // z = h + ent_feat (fp16)
__device__ __half g_wx16[(size_t)V_*H_];    // Wx in fp16

__device__ __forceinline__ uint32_t pack_h2(float a, float b) {
    __half2 h = __floats2half2_rn(a, b);
    return *reinterpret_cast<uint32_t*>(&h);
}
__device__ __forceinline__ float tanh_fast(float x) {
    float y;
    asm("tanh.approx.f32 %0, %1;" : "=f"(y) : "f"(x));
    return y;
}
__device__ __forceinline__ float sigmoid_fast(float x) {
    return 0.5f * tanh_fast(0.5f * x) + 0.5f;
}

// ---------------- K0: Wx -> fp16 ----------------
__global__ void k_cvt(const float* __restrict__ src, __half* __restrict__ dst, int n) {
    int i = blockIdx.x * blockDim.x + threadIdx.x;
    if (i < n) dst[i] = __float2half(src[i]);
}

// ---------------- K1: xw = embed[tok] @ Wih^T + bih + bhh, permuted layout ----------------
__global__ void k_xw(const int* __restrict__ tokens, const float* __restrict__ embed,
                     const float* __restrict__ Wih, const float* __restrict__ bih,
                     const float* __restrict__ bhh) {
    __shared__ __align__(16) float xs[16][D_];
    int b = blockIdx.y, t0 = blockIdx.x * 16, n = threadIdx.x;
    for (int i = n; i < 16 * D_; i += 512) {
        int r = i / D_, d = i - r * D_;
        xs[r][d] = embed[(size_t)tokens[b * T_ + t0 + r] * D_ + d];
    }
    __syncthreads();
    float acc[16];
#pragma unroll
    for (int r = 0; r < 16; r++) acc[r] = 0.f;
    const float4* wr = reinterpret_cast<const float4*>(Wih + (size_t)n * D_);
#pragma unroll 5
    for (int d4 = 0; d4 < D_ / 4; d4++) {
        float4 w = __ldg(wr + d4);
#pragma unroll
        for (int r = 0; r < 16; r++) {
            float4 x = *reinterpret_cast<const float4*>(&xs[r][d4 * 4]);
            acc[r] += w.x * x.x + w.y * x.y + w.z * x.z + w.w * x.w;
        }
    }
    float bb = bih[n] + bhh[n];
    int gate = n >> 7, dd = n & 127;
    for (int r = 0; r < 16; r++)
        g_xwp[(((size_t)(t0 + r) * H_ + dd) << 4) + b * 4 + gate] = acc[r] + bb;
}

// ---------------- K2: sequential LSTM, gate-permuted, 1 barrier/step ----------------
__global__ void __launch_bounds__(512, 1) k_lstm4(const float* __restrict__ Whh) {
    __shared__ __half2 hbuf[2][4][72];
    int tid = threadIdx.x, wid = tid >> 5, lane = tid & 31;

    uint32_t afr[2][8][4];
#pragma unroll
    for (int m = 0; m < 2; m++)
#pragma unroll
        for (int ks = 0; ks < 8; ks++) {
            int rl = (m ? 256 : 0) + 8 * wid + (lane >> 2);
            int rh = rl + 128;
            int k0 = 16 * ks + (lane & 3) * 2;
            float2 wl0 = __ldg(reinterpret_cast<const float2*>(Whh + (size_t)rl * H_ + k0));
            float2 wh0 = __ldg(reinterpret_cast<const float2*>(Whh + (size_t)rh * H_ + k0));
            float2 wl8 = __ldg(reinterpret_cast<const float2*>(Whh + (size_t)rl * H_ + k0 + 8));
            float2 wh8 = __ldg(reinterpret_cast<const float2*>(Whh + (size_t)rh * H_ + k0 + 8));
            afr[m][ks][0] = pack_h2(wl0.x, wl0.y);
            afr[m][ks][1] = pack_h2(wh0.x, wh0.y);
            afr[m][ks][2] = pack_h2(wl8.x, wl8.y);
            afr[m][ks][3] = pack_h2(wh8.x, wh8.y);
        }

    if (tid < 288) {
        __half2 z = __half2half2(__float2half(0.f));
        (&hbuf[0][0][0])[tid] = z;
    }
    int bq = lane & 3;
    int hd = 8 * wid + (lane >> 2);
    int myb = ((bq & 1) << 1) | (bq >> 1);
    int sel = bq >> 1;
    int bb = (lane >> 2) & 3;
    int kq = lane & 3;
    float c = 0.f;
    __syncthreads();

    const float4* xwp4 = reinterpret_cast<const float4*>(g_xwp);
    float4 xa = __ldg(&xwp4[(size_t)hd * 4 + myb]);

    for (int t = 0; t < T_; t++) {
        int buf = t & 1;
        float acc0[4] = {0.f, 0.f, 0.f, 0.f};
        float acc1[4] = {0.f, 0.f, 0.f, 0.f};
#pragma unroll
        for (int ks = 0; ks < 8; ks++) {
            uint32_t b0 = *reinterpret_cast<const uint32_t*>(&hbuf[buf][bb][ks * 8 + kq]);
            uint32_t b1 = *reinterpret_cast<const uint32_t*>(&hbuf[buf][bb][ks * 8 + kq + 4]);
            asm volatile(
                "mma.sync.aligned.m16n8k16.row.col.f32.f16.f16.f32 "
                "{%0,%1,%2,%3}, {%4,%5,%6,%7}, {%8,%9}, {%0,%1,%2,%3};"
                : "+f"(acc0[0]), "+f"(acc0[1]), "+f"(acc0[2]), "+f"(acc0[3])
                : "r"(afr[0][ks][0]), "r"(afr[0][ks][1]),
                  "r"(afr[0][ks][2]), "r"(afr[0][ks][3]),
                  "r"(b0), "r"(b1));
            asm volatile(
                "mma.sync.aligned.m16n8k16.row.col.f32.f16.f16.f32 "
                "{%0,%1,%2,%3}, {%4,%5,%6,%7}, {%8,%9}, {%0,%1,%2,%3};"
                : "+f"(acc1[0]), "+f"(acc1[1]), "+f"(acc1[2]), "+f"(acc1[3])
                : "r"(afr[1][ks][0]), "r"(afr[1][ks][1]),
                  "r"(afr[1][ks][2]), "r"(afr[1][ks][3]),
                  "r"(b0), "r"(b1));
        }
        float4 xn = make_float4(0.f, 0.f, 0.f, 0.f);
        if (t + 1 < T_)
            xn = __ldg(&xwp4[((size_t)(t + 1) * H_ + hd) * 4 + myb]);

        float gi = (sel ? acc0[1] : acc0[0]) + xa.x;
        float gf = (sel ? acc0[3] : acc0[2]) + xa.y;
        float gg = (sel ? acc1[1] : acc1[0]) + xa.z;
        float go = (sel ? acc1[3] : acc1[2]) + xa.w;
        float si = sigmoid_fast(gi);
        float sf = sigmoid_fast(gf);
        float so = sigmoid_fast(go);
        c = sf * c + si * tanh_fast(gg);
        float h = so * tanh_fast(c);
        g_h[(size_t)(myb * T_ + t) * H_ + hd] = h;
        reinterpret_cast<__half*>(&hbuf[buf ^ 1][myb][0])[hd] = __float2half(h);
        __syncthreads();
        xa = xn;
    }
}

// ---------------- K3: veh = We@h, vdh = Wd@h, + pred_r + ||h||^2 ----------------
__global__ void k_vw(const float* __restrict__ We, const float* __restrict__ Wd,
                     const float* __restrict__ Wr, const float* __restrict__ br,
                     float* __restrict__ out_pr) {
    __shared__ __align__(16) float hsm[16][H_];
    __shared__ float wr_s[H_];
    int row0 = blockIdx.x * 16;
    int tid = threadIdx.x;
    for (int i = tid; i < 16 * H_; i += 256)
        hsm[i >> 7][i & 127] = g_h[(size_t)row0 * H_ + i];
    if (tid < H_) wr_s[tid] = Wr[tid];
    __syncthreads();
    int k = tid & 127;
    const float* M = (tid < 128) ? We : Wd;
    float* O = (tid < 128) ? g_weh : g_wdh;
    const float4* mrow = reinterpret_cast<const float4*>(M + (size_t)k * H_);
    float acc[16];
#pragma unroll
    for (int r = 0; r < 16; r++) acc[r] = 0.f;
#pragma unroll 4
    for (int k4 = 0; k4 < H_ / 4; k4++) {
        float4 w = __ldg(mrow + k4);
#pragma unroll
        for (int r = 0; r < 16; r++) {
            float4 h = *reinterpret_cast<const float4*>(&hsm[r][k4 * 4]);
            acc[r] += w.x * h.x + w.y * h.y + w.z * h.z + w.w * h.w;
        }
    }
    for (int r = 0; r < 16; r++)
        O[(size_t)(row0 + r) * H_ + k] = acc[r];

    int warp = tid >> 5, lane = tid & 31;
    float brv = __ldg(br);
#pragma unroll
    for (int rr = 0; rr < 2; rr++) {
        int r = warp * 2 + rr;
        float h0 = hsm[r][lane],      h1 = hsm[r][lane + 32];
        float h2 = hsm[r][lane + 64], h3 = hsm[r][lane + 96];
        float p = h0 * wr_s[lane]      + h1 * wr_s[lane + 32]
                + h2 * wr_s[lane + 64] + h3 * wr_s[lane + 96];
        float s = h0 * h0 + h1 * h1 + h2 * h2 + h3 * h3;
#pragma unroll
        for (int o = 16; o; o >>= 1) {
            p += __shfl_down_sync(0xffffffffu, p, o);
            s += __shfl_down_sync(0xffffffffu, s, o);
        }
        if (lane == 0) {
            out_pr[row0 + r] = 1.f / (1.f + __expf(-(p + brv)));
            g_hh[row0 + r] = s;
        }
    }
}

// ---------------- K4: sequential entity recurrence, 2 barriers/step ----------------
// ||u||^2 computed analytically: ||ent||=1 -> d^2 + 2d(1-d)(ent.h) + (1-d)^2||h||^2.
// ent.vdh reduced on warps 0-3, ent.h on warps 4-7 (parallel chains).
__global__ void k_ent2(const int* __restrict__ eids, const int* __restrict__ sids,
                       const float* __restrict__ ents0, const float* __restrict__ lamp,
                       float* __restrict__ out_pe) {
    __shared__ float entsT[H_][E_ + 1];
    __shared__ float dists[E_];
    __shared__ float veh_s[H_], vdh_s[H_], h_s[H_], last_s[H_];
    __shared__ float red2[256];
    __shared__ float nred[4];    // ent . vdh partials
    __shared__ float nred2[4];   // ent . h partials
    int b = blockIdx.x, tid = threadIdx.x;
    float lam = *lamp;
    for (int i = tid; i < E_ * H_; i += 256) {
        int e = i >> 7, j = i & 127;
        entsT[j][e] = ents0[(size_t)(b * E_ + e) * H_ + j];
    }
    if (tid < E_) dists[tid] = 0.f;
    if (tid < H_) last_s[tid] = ents0[(size_t)b * E_ * H_ + tid];
    __syncthreads();
    int q = tid >> 6, e = tid & 63;
    int lane = tid & 31, warp = tid >> 5;
    int jd = tid & 127;   // dim for dot duty

    // prefetch t=0
    float pv = 0.f, pd = 0.f, ph = 0.f;
    {
        size_t bt0 = (size_t)b * T_ * H_;
        if (tid < H_) {
            pv = __ldg(&g_weh[bt0 + tid]);
            pd = __ldg(&g_wdh[bt0 + tid]);
            ph = __ldg(&g_h[bt0 + tid]);
        }
    }
    int peid = __ldg(&eids[b * T_]);
    float psid = (float)__ldg(&sids[b * T_]);
    float phh = __ldg(&g_hh[b * T_]);

    for (int t = 0; t < T_; t++) {
        int bt = b * T_ + t;
        if (tid < H_) { veh_s[tid] = pv; vdh_s[tid] = pd; h_s[tid] = ph; }
        int eid = peid;
        float sid = psid;
        float hh = phh;
        __syncthreads();  // S1: staging + prev-step updates visible
        // prefetch t+1
        if (t + 1 < T_) {
            size_t bt1 = (size_t)(bt + 1) * H_;
            if (tid < H_) {
                pv = __ldg(&g_weh[bt1 + tid]);
                pd = __ldg(&g_wdh[bt1 + tid]);
                ph = __ldg(&g_h[bt1 + tid]);
            }
            peid = __ldg(&eids[bt + 1]);
            psid = (float)__ldg(&sids[bt + 1]);
            phh = __ldg(&g_hh[bt + 1]);
        }
        // phase 1: exp term (reads pre-update dists)
        float expterm = 0.f;
        if (tid < E_) expterm = expf((dists[tid] - sid) * lam);
        // pred_e partials: thread (q,e), 4 accumulators
        float p0 = 0.f, p1 = 0.f, p2 = 0.f, p3 = 0.f;
#pragma unroll
        for (int jj = 0; jj < 8; jj++) {
            int j = q * 32 + jj * 4;
            p0 += entsT[j][e]     * veh_s[j];
            p1 += entsT[j + 1][e] * veh_s[j + 1];
            p2 += entsT[j + 2][e] * veh_s[j + 2];
            p3 += entsT[j + 3][e] * veh_s[j + 3];
        }
        red2[tid] = (p0 + p1) + (p2 + p3);
        // dual dots: warps 0-3 ent.vdh, warps 4-7 ent.h
        float ent_val = entsT[jd][eid];
        float d = ent_val * ((tid < 128) ? vdh_s[jd] : h_s[jd]);
#pragma unroll
        for (int o = 16; o; o >>= 1) d += __shfl_down_sync(0xffffffffu, d, o);
        if (lane == 0) {
            if (warp < 4) nred[warp] = d;
            else          nred2[warp - 4] = d;
        }
        __syncthreads();  // S2
        // phase 2
        if (tid < E_) {
            out_pe[(size_t)bt * E_ + tid] =
                red2[tid] + red2[tid + 64] + red2[tid + 128] + red2[tid + 192] + expterm;
        }
        float dotdv = nred[0] + nred[1] + nred[2] + nred[3];
        float doteh = nred2[0] + nred2[1] + nred2[2] + nred2[3];
        float delta = 1.f / (1.f + __expf(-dotdv));
        float omd = 1.f - delta;
        float n2 = delta * delta + 2.f * delta * omd * doteh + omd * omd * hh;
        float rn = rsqrtf(n2);
        if (tid < H_) {
            float u = delta * ent_val + omd * h_s[tid];
            float un = u * rn;
            float fs = (eid > 0) ? un : last_s[tid];
            g_fsrc[(size_t)bt * H_ + tid] = fs;
            entsT[tid][eid] = un;
            last_s[tid] = un;
        }
        if (tid == 0) { dists[eid] = sid; g_sel[bt] = (eid > 0) ? 1 : 0; }
        // next S1 orders these writes before next reads
    }
}

// ---------------- K5: ent_feat + z (fp16) ----------------
__global__ void k_feat(const float* __restrict__ WTe, const float* __restrict__ WTc) {
    __shared__ __align__(16) float fs[8][H_];
    int row0 = blockIdx.x * 8;
    int j = threadIdx.x;
    for (int i = j; i < 8 * H_; i += 128)
        fs[i >> 7][i & 127] = g_fsrc[(size_t)row0 * H_ + i];
    __syncthreads();
    float acc_e[8], acc_c[8];
#pragma unroll
    for (int r = 0; r < 8; r++) { acc_e[r] = 0.f; acc_c[r] = 0.f; }
    const float4* we4 = reinterpret_cast<const float4*>(WTe + (size_t)j * H_);
    const float4* wc4 = reinterpret_cast<const float4*>(WTc + (size_t)j * H_);
#pragma unroll 4
    for (int k4 = 0; k4 < H_ / 4; k4++) {
        float4 we = __ldg(we4 + k4);
        float4 wc = __ldg(wc4 + k4);
#pragma unroll
        for (int r = 0; r < 8; r++) {
            float4 f = *reinterpret_cast<const float4*>(&fs[r][k4 * 4]);
            acc_e[r] += we.x * f.x + we.y * f.y + we.z * f.z + we.w * f.w;
            acc_c[r] += wc.x * f.x + wc.y * f.y + wc.z * f.z + wc.w * f.w;
        }
    }
    for (int r = 0; r < 8; r++) {
        int bt = row0 + r;
        float feat = g_sel[bt] ? acc_e[r] : acc_c[r];
        float z = g_h[(size_t)bt * H_ + j] + feat;
        g_z16[(size_t)bt * H_ + j] = __float2half(z);
    }
}

// ---------------- K6: logits = z @ Wx^T + bx, 128x128 tiles ----------------
__global__ void __launch_bounds__(256, 2) k_logits(const float* __restrict__ bx,
                                                   float* __restrict__ out) {
    extern __shared__ __align__(16) __half smemh[];
    __half (*sA)[128] = reinterpret_cast<__half (*)[128]>(smemh);
    __half (*sB)[128] = reinterpret_cast<__half (*)[128]>(smemh + 128 * 128);
    int tid = threadIdx.x;
    int m0 = blockIdx.y * 128;
    int n0 = blockIdx.x * 128;
    {
        int r = tid >> 1;
        int cbase = (tid & 1) * 8;
        const uint4* src = reinterpret_cast<const uint4*>(g_z16) + (size_t)(m0 + r) * 16;
#pragma unroll
        for (int i = 0; i < 8; i++) {
            int c = cbase + i;
            uint4 v = src[c];
            *reinterpret_cast<uint4*>(&sA[r][(c ^ (r & 7)) << 3]) = v;
        }
    }
    {
        int r = tid >> 1;
        int cbase = (tid & 1) * 8;
        int v_ = n0 + r;
        const uint4* src = reinterpret_cast<const uint4*>(g_wx16) + (size_t)v_ * 16;
#pragma unroll
        for (int i = 0; i < 8; i++) {
            int c = cbase + i;
            uint4 v;
            if (v_ < V_) v = src[c];
            else { v.x = 0u; v.y = 0u; v.z = 0u; v.w = 0u; }
            *reinterpret_cast<uint4*>(&sB[r][(c ^ (r & 7)) << 3]) = v;
        }
    }
    __syncthreads();

    int lane = tid & 31, warp = tid >> 5;
    int wm = warp >> 1, wn = warp & 1;
    float acc[2][8][4];
#pragma unroll
    for (int mt = 0; mt < 2; mt++)
#pragma unroll
        for (int nt = 0; nt < 8; nt++)
#pragma unroll
            for (int i = 0; i < 4; i++) acc[mt][nt][i] = 0.f;

#pragma unroll
    for (int ks = 0; ks < 8; ks++) {
        uint32_t afrag[2][4];
#pragma unroll
        for (int mt = 0; mt < 2; mt++) {
            int row = wm * 32 + mt * 16 + (lane & 15);
            int chunk = ks * 2 + (lane >> 4);
            unsigned addr = (unsigned)__cvta_generic_to_shared(&sA[row][(chunk ^ (row & 7)) << 3]);
            asm volatile("ldmatrix.sync.aligned.m8n8.x4.shared.b16 {%0,%1,%2,%3}, [%4];"
                         : "=r"(afrag[mt][0]), "=r"(afrag[mt][1]),
                           "=r"(afrag[mt][2]), "=r"(afrag[mt][3]) : "r"(addr));
        }
        uint32_t bfrag[8][2];
#pragma unroll
        for (int nt = 0; nt < 8; nt++) {
            int row = wn * 64 + nt * 8 + (lane & 7);
            int chunk = ks * 2 + ((lane >> 3) & 1);
            unsigned addr = (unsigned)__cvta_generic_to_shared(&sB[row][(chunk ^ (row & 7)) << 3]);
            asm volatile("ldmatrix.sync.aligned.m8n8.x2.shared.b16 {%0,%1}, [%2];"
                         : "=r"(bfrag[nt][0]), "=r"(bfrag[nt][1]) : "r"(addr));
        }
#pragma unroll
        for (int mt = 0; mt < 2; mt++)
#pragma unroll
            for (int nt = 0; nt < 8; nt++) {
                asm volatile(
                    "mma.sync.aligned.m16n8k16.row.col.f32.f16.f16.f32 "
                    "{%0,%1,%2,%3}, {%4,%5,%6,%7}, {%8,%9}, {%0,%1,%2,%3};"
                    : "+f"(acc[mt][nt][0]), "+f"(acc[mt][nt][1]),
                      "+f"(acc[mt][nt][2]), "+f"(acc[mt][nt][3])
                    : "r"(afrag[mt][0]), "r"(afrag[mt][1]),
                      "r"(afrag[mt][2]), "r"(afrag[mt][3]),
                      "r"(bfrag[nt][0]), "r"(bfrag[nt][1]));
            }
    }
    int rrow = lane >> 2, col = (lane & 3) * 2;
#pragma unroll
    for (int mt = 0; mt < 2; mt++) {
#pragma unroll
        for (int nt = 0; nt < 8; nt++) {
            size_t gm = (size_t)(m0 + wm * 32 + mt * 16 + rrow);
            int gv = n0 + wn * 64 + nt * 8 + col;
            float* a = acc[mt][nt];
            if (gv < V_) {
                float b0 = bx[gv];
                out[gm * V_ + gv]       = a[0] + b0;
                out[(gm + 8) * V_ + gv] = a[2] + b0;
            }
            if (gv + 1 < V_) {
                float b1 = bx[gv + 1];
                out[gm * V_ + gv + 1]       = a[1] + b1;
                out[(gm + 8) * V_ + gv + 1] = a[3] + b1;
            }
        }
    }
}

// ---------------- launch ----------------
extern "C" void kernel_launch(void* const* d_in, const int* in_sizes, int n_in,
                              void* d_out, int out_size) {
    const int*   tokens = (const int*)d_in[0];
    const int*   eids   = (const int*)d_in[1];
    const int*   sids   = (const int*)d_in[2];
    const float* embed  = (const float*)d_in[3];
    const float* Wih    = (const float*)d_in[4];
    const float* Whh    = (const float*)d_in[5];
    const float* bih    = (const float*)d_in[6];
    const float* bhh    = (const float*)d_in[7];
    const float* Wr     = (const float*)d_in[8];
    const float* br     = (const float*)d_in[9];
    const float* We     = (const float*)d_in[10];
    const float* Wd     = (const float*)d_in[11];
    const float* WTe    = (const float*)d_in[12];
    const float* WTc    = (const float*)d_in[13];
    const float* Wx     = (const float*)d_in[14];
    const float* bx     = (const float*)d_in[15];
    const float* ents0  = (const float*)d_in[16];
    const float* lam    = (const float*)d_in[17];
    float* out = (float*)d_out;

    const size_t OFF_R = (size_t)B_ * T_ * V_;
    const size_t OFF_E = OFF_R + (size_t)B_ * T_;

    __half* wx16;
    cudaGetSymbolAddress((void**)&wx16, g_wx16);

    static int attr_set = 0;
    if (!attr_set) {
        cudaFuncSetAttribute(k_logits, cudaFuncAttributeMaxDynamicSharedMemorySize, 65536);
        attr_set = 1;
    }

    int nwx = V_ * H_;
    k_cvt<<<(nwx + 255) / 256, 256>>>(Wx, wx16, nwx);
    k_xw<<<dim3(T_ / 16, B_), 512>>>(tokens, embed, Wih, bih, bhh);
    k_lstm4<<<1, 512>>>(Whh);
    k_vw<<<(B_ * T_) / 16, 256>>>(We, Wd, Wr, br, out + OFF_R);
    k_ent2<<<B_, 256>>>(eids, sids, ents0, lam, out + OFF_E);
    k_feat<<<(B_ * T_) / 8, 128>>>(WTe, WTc);
    k_logits<<<dim3((V_ + 127) / 128, (B_ * T_) / 128), 256, 65536>>>(bx, out);
}